// round 2
// baseline (speedup 1.0000x reference)
#include <cuda_runtime.h>

// Problem constants
#define BB 4
#define CC 256
#define HWIN 1024      // 32*32
#define NQ 4225        // 65*65
#define NCO 192        // 128 shortcut + 64 q

typedef unsigned long long ull;

// ---------------- scratch (device globals) -----------------------------------
__device__ float g_xr[BB * CC * HWIN];        // BN+ReLU output [b][c][p]
__device__ float g_wt[CC * 9 * NCO];          // repacked conv weights [c][tap][co]
__device__ float g_q[BB * 64 * NQ];           // q conv output  [b][d][n]
__device__ float g_attO[BB * 64 * NQ];        // attention out  [b][d][n]
__device__ float g_kp[BB * 8 * 512 * 16];     // k pair-packed [b][h][j2][d(8)][2]
__device__ float g_vp[BB * 8 * 512 * 16];     // v pair-packed

// ---------------- f32x2 helpers ---------------------------------------------
__device__ __forceinline__ ull pk2(float a, float b) {
    ull r; asm("mov.b64 %0, {%1,%2};" : "=l"(r) : "f"(a), "f"(b)); return r;
}
__device__ __forceinline__ void upk2(ull v, float& a, float& b) {
    asm("mov.b64 {%0,%1}, %2;" : "=f"(a), "=f"(b) : "l"(v));
}
__device__ __forceinline__ ull ffma2(ull a, ull b, ull c) {
    ull r; asm("fma.rn.f32x2 %0, %1, %2, %3;" : "=l"(r) : "l"(a), "l"(b), "l"(c)); return r;
}
__device__ __forceinline__ ull fmul2(ull a, ull b) {
    ull r; asm("mul.rn.f32x2 %0, %1, %2;" : "=l"(r) : "l"(a), "l"(b)); return r;
}
__device__ __forceinline__ ull fadd2(ull a, ull b) {
    ull r; asm("add.rn.f32x2 %0, %1, %2;" : "=l"(r) : "l"(a), "l"(b)); return r;
}
__device__ __forceinline__ float ex2f(float x) {
    float r; asm("ex2.approx.f32 %0, %1;" : "=f"(r) : "f"(x)); return r;
}
__device__ __forceinline__ float laneof(const ull* A, int i) {
    float lo, hi; upk2(A[i >> 1], lo, hi); return (i & 1) ? hi : lo;
}

// ---------------- kernel 1: BN (inference) + ReLU ----------------------------
__global__ void __launch_bounds__(256) bn_kernel(
    const float* __restrict__ x, const float* __restrict__ gamma,
    const float* __restrict__ beta, const float* __restrict__ rmean,
    const float* __restrict__ rvar)
{
    int idx = blockIdx.x * 256 + threadIdx.x;
    int c = (idx >> 10) & 255;
    float a = gamma[c] * rsqrtf(rvar[c] + 1e-5f);
    float bia = beta[c] - rmean[c] * a;
    g_xr[idx] = fmaxf(fmaf(x[idx], a, bia), 0.f);
}

// ---------------- kernel 2: repack + FLIP conv-transpose weights -------------
__global__ void __launch_bounds__(256) repack_kernel(
    const float* __restrict__ w_sc, const float* __restrict__ w_q)
{
    int i = blockIdx.x * 256 + threadIdx.x;            // [0, 442368)
    int c = i / (9 * NCO);
    int r = i - c * (9 * NCO);
    int t = r / NCO;
    int co = r - t * NCO;
    int s = 8 - t;   // spatial flip
    float v;
    if (co < 128) v = w_sc[(c * 128 + co) * 9 + s];
    else          v = w_q[(c * 64 + (co - 128)) * 9 + s];
    g_wt[i] = v;
}

// ---------------- kernel 3: k/v 1x1 projections, pair-packed -----------------
__global__ void __launch_bounds__(256) kv_kernel(
    const float* __restrict__ wk, const float* __restrict__ wv)
{
    const int b = blockIdx.y;
    const int p = blockIdx.x * 32 + (threadIdx.x & 31);
    const int dg = threadIdx.x >> 5;                   // 0..7
    const float* wbase = (dg < 4) ? (wk + dg * 16 * CC) : (wv + (dg - 4) * 16 * CC);
    const float* xp = g_xr + b * (CC * HWIN) + p;

    float acc[16];
#pragma unroll
    for (int i = 0; i < 16; i++) acc[i] = 0.f;

    for (int c = 0; c < CC; c += 4) {
        float x0 = xp[(c + 0) * HWIN];
        float x1 = xp[(c + 1) * HWIN];
        float x2 = xp[(c + 2) * HWIN];
        float x3 = xp[(c + 3) * HWIN];
#pragma unroll
        for (int i = 0; i < 16; i++) {
            float4 w4 = *(const float4*)(wbase + i * CC + c);
            acc[i] = fmaf(w4.x, x0, fmaf(w4.y, x1, fmaf(w4.z, x2, fmaf(w4.w, x3, acc[i]))));
        }
    }
    const int par = p & 1, j2 = p >> 1;
#pragma unroll
    for (int i = 0; i < 16; i++) {
        int d = dg * 16 + i;
        if (d < 64) {
            int hh = d >> 3, dd = d & 7;
            g_kp[(b * 8 + hh) * 8192 + j2 * 16 + dd * 2 + par] = acc[i];
        } else {
            int d2 = d - 64, hh = d2 >> 3, dd = d2 & 7;
            g_vp[(b * 8 + hh) * 8192 + j2 * 16 + dd * 2 + par] = acc[i];
        }
    }
}

// ---------------- kernel 4: fused ConvTranspose, f32x2 tap-separated ---------
// Per thread (one co), per x-half: three packed accumulator sets over aligned
// input pairs. Lane shift between tap-0 and tap-2 contributions applied once
// at recombine. E0 = sum w(kxt=0)*pair, E2 = sum w(kxt=2)*pair, O = w(kxt=1).
template <bool EXTRA>
__device__ __forceinline__ void load_pairs(ull (&P)[9], const float* p, bool valid) {
    if (valid) {
        const ulonglong2* p2 = (const ulonglong2*)p;
#pragma unroll
        for (int q = 0; q < 4; q++) {
            ulonglong2 t = p2[q];
            P[2 * q] = t.x; P[2 * q + 1] = t.y;
        }
        P[8] = EXTRA ? pk2(__ldg(p + 16), 0.f) : 0ull;
    } else {
#pragma unroll
        for (int q = 0; q < 9; q++) P[q] = 0ull;
    }
}

template <int XH>
__device__ __forceinline__ void conv_path(float* __restrict__ out, float* sAcc) {
    constexpr int NXU = XH ? 32 : 33;
    constexpr int X0  = XH ? 33 : 0;
    constexpr int JB  = XH ? 16 : 0;
    constexpr bool EXTRA = (XH == 0);  // half0 needs row[16] in pair 8

    const int y = blockIdx.x;
    const int b = blockIdx.y;
    const int co = threadIdx.x;                        // 0..191
    const float* xrb = g_xr + b * (CC * HWIN);

    ull E0[9], E2[9], O[8];
#pragma unroll
    for (int i = 0; i < 9; i++) { E0[i] = 0ull; E2[i] = 0ull; }
#pragma unroll
    for (int i = 0; i < 8; i++) O[i] = 0ull;

    if ((y & 1) == 0) {
        const int iyA = y >> 1;        // flipped ky-tap 0
        const int iyB = iyA - 1;       // flipped ky-tap 2
        const bool vA = (iyA <= 31);
        const bool vB = (iyB >= 0);
        for (int c = 0; c < CC; c++) {
            const float* wp = g_wt + (c * 9) * NCO + co;
            ull wA0 = pk2(wp[0],        wp[0]);
            ull wA1 = pk2(wp[NCO],      wp[NCO]);
            ull wA2 = pk2(wp[2 * NCO],  wp[2 * NCO]);
            ull wB0 = pk2(wp[6 * NCO],  wp[6 * NCO]);
            ull wB1 = pk2(wp[7 * NCO],  wp[7 * NCO]);
            ull wB2 = pk2(wp[8 * NCO],  wp[8 * NCO]);
            ull PA[9], PB[9];
            load_pairs<EXTRA>(PA, xrb + (c * 32 + iyA) * 32 + JB, vA);
            load_pairs<EXTRA>(PB, xrb + (c * 32 + iyB) * 32 + JB, vB);
#pragma unroll
            for (int jj = 0; jj < 9; jj++) {
                E0[jj] = ffma2(wA0, PA[jj], E0[jj]);
                E0[jj] = ffma2(wB0, PB[jj], E0[jj]);
                E2[jj] = ffma2(wA2, PA[jj], E2[jj]);
                E2[jj] = ffma2(wB2, PB[jj], E2[jj]);
            }
#pragma unroll
            for (int jj = 0; jj < 8; jj++) {
                O[jj] = ffma2(wA1, PA[jj], O[jj]);
                O[jj] = ffma2(wB1, PB[jj], O[jj]);
            }
        }
    } else {
        const int iyC = y >> 1;        // flipped ky-tap 1, always valid
        for (int c = 0; c < CC; c++) {
            const float* wp = g_wt + (c * 9) * NCO + co;
            ull w0 = pk2(wp[3 * NCO], wp[3 * NCO]);
            ull w1 = pk2(wp[4 * NCO], wp[4 * NCO]);
            ull w2 = pk2(wp[5 * NCO], wp[5 * NCO]);
            ull PC[9];
            load_pairs<EXTRA>(PC, xrb + (c * 32 + iyC) * 32 + JB, true);
#pragma unroll
            for (int jj = 0; jj < 9; jj++) {
                E0[jj] = ffma2(w0, PC[jj], E0[jj]);
                E2[jj] = ffma2(w2, PC[jj], E2[jj]);
            }
#pragma unroll
            for (int jj = 0; jj < 8; jj++)
                O[jj] = ffma2(w1, PC[jj], O[jj]);
        }
    }

    // Recombine (lane-shift applied once) + smem transpose
#pragma unroll
    for (int u = 0; u < NXU; u++) {
        float v;
        if (XH == 0) {
            if ((u & 1) == 0) {                   // even x = u
                const int je = u >> 1;
                v = laneof(E0, je) + ((je > 0) ? laneof(E2, je - 1) : 0.f);
            } else {                              // odd x
                v = laneof(O, (u - 1) >> 1);
            }
        } else {
            if ((u & 1) == 0) {                   // x = 33+u odd
                v = laneof(O, u >> 1);
            } else {                              // x = 33+u even
                const int je = (u - 1) >> 1;
                v = laneof(E2, je) + laneof(E0, je + 1);
            }
        }
        sAcc[co * 33 + u] = v;
    }
    __syncthreads();
    const int total = NCO * NXU;
    for (int i = threadIdx.x; i < total; i += NCO) {
        int c2 = i / NXU, u2 = i - c2 * NXU;
        float v = sAcc[c2 * 33 + u2];
        int n = y * 65 + (X0 + u2);
        if (c2 < 128) out[(b * 128 + c2) * NQ + n] = v;
        else          g_q[(b * 64 + (c2 - 128)) * NQ + n] = v;
    }
}

__global__ void __launch_bounds__(192) convt_kernel(float* __restrict__ out) {
    __shared__ float sAcc[NCO * 33];
    if (blockIdx.z == 0) conv_path<0>(out, sAcc);
    else                 conv_path<1>(out, sAcc);
}

// ---------------- kernel 5: attention, no-max softmax (scores bounded) -------
__global__ void __launch_bounds__(256) attn_kernel() {
    __shared__ float4 sk[1024];   // 256 key-pairs * 16 floats = 16KB
    __shared__ float4 sv[1024];
    const int qt = blockIdx.x, h = blockIdx.y, b = blockIdx.z;
    const int t = threadIdx.x;
    const int n = qt * 256 + t;
    const bool act = (n < NQ);

    // fold 1/sqrt(dk) * log2(e) into q
    const float sc = 0.35355339059327373f * 1.4426950408889634f;
    ull q2[8];
#pragma unroll
    for (int d = 0; d < 8; d++) {
        float qv = act ? g_q[(b * 64 + h * 8 + d) * NQ + n] * sc : 0.f;
        q2[d] = pk2(qv, qv);
    }
    ull l2 = 0ull;
    ull acc2[8];
#pragma unroll
    for (int d = 0; d < 8; d++) acc2[d] = 0ull;

    const float4* gk = (const float4*)(g_kp + (b * 8 + h) * 8192);
    const float4* gv = (const float4*)(g_vp + (b * 8 + h) * 8192);

    for (int ch = 0; ch < 2; ch++) {
        __syncthreads();
        for (int i = t; i < 1024; i += 256) {
            sk[i] = gk[ch * 1024 + i];
            sv[i] = gv[ch * 1024 + i];
        }
        __syncthreads();
        const ulonglong2* k2 = (const ulonglong2*)sk;
        const ulonglong2* v2 = (const ulonglong2*)sv;
        for (int j2 = 0; j2 < 256; j2++) {
            ulonglong2 ka = k2[j2 * 4 + 0];
            ulonglong2 kb = k2[j2 * 4 + 1];
            ulonglong2 kc = k2[j2 * 4 + 2];
            ulonglong2 kd = k2[j2 * 4 + 3];
            ull s2 = fmul2(q2[0], ka.x);
            s2 = ffma2(q2[1], ka.y, s2);
            s2 = ffma2(q2[2], kb.x, s2);
            s2 = ffma2(q2[3], kb.y, s2);
            s2 = ffma2(q2[4], kc.x, s2);
            s2 = ffma2(q2[5], kc.y, s2);
            s2 = ffma2(q2[6], kd.x, s2);
            s2 = ffma2(q2[7], kd.y, s2);
            float s0, s1; upk2(s2, s0, s1);
            float p0 = ex2f(s0);
            float p1 = ex2f(s1);
            ull p2 = pk2(p0, p1);
            l2 = fadd2(l2, p2);
            ulonglong2 va = v2[j2 * 4 + 0];
            ulonglong2 vb = v2[j2 * 4 + 1];
            ulonglong2 vc = v2[j2 * 4 + 2];
            ulonglong2 vd = v2[j2 * 4 + 3];
            acc2[0] = ffma2(p2, va.x, acc2[0]);
            acc2[1] = ffma2(p2, va.y, acc2[1]);
            acc2[2] = ffma2(p2, vb.x, acc2[2]);
            acc2[3] = ffma2(p2, vb.y, acc2[3]);
            acc2[4] = ffma2(p2, vc.x, acc2[4]);
            acc2[5] = ffma2(p2, vc.y, acc2[5]);
            acc2[6] = ffma2(p2, vd.x, acc2[6]);
            acc2[7] = ffma2(p2, vd.y, acc2[7]);
        }
    }
    if (act) {
        float l0, l1; upk2(l2, l0, l1);
        float inv = 1.f / (l0 + l1);
#pragma unroll
        for (int d = 0; d < 8; d++) {
            float a0, a1; upk2(acc2[d], a0, a1);
            g_attO[(b * 64 + h * 8 + d) * NQ + n] = (a0 + a1) * inv;
        }
    }
}

// ---------------- kernel 6: output projection + residual add (f32x2) ---------
__global__ void __launch_bounds__(256) proj_kernel(
    const float* __restrict__ w_o, float* __restrict__ out)
{
    __shared__ float sw[128 * 64];
    for (int i = threadIdx.x; i < 8192; i += 256) sw[i] = w_o[i];
    __syncthreads();

    const int b = blockIdx.y;
    const int nl = threadIdx.x & 63;
    const int cog = threadIdx.x >> 6;                  // 0..3 (32 co each)
    const int n = blockIdx.x * 64 + nl;
    if (n >= NQ) return;

    ull a2[32];
#pragma unroll
    for (int dd = 0; dd < 32; dd++) {
        float a0 = g_attO[(b * 64 + 2 * dd) * NQ + n];
        float a1 = g_attO[(b * 64 + 2 * dd + 1) * NQ + n];
        a2[dd] = pk2(a0, a1);
    }

    for (int c0 = 0; c0 < 32; c0++) {
        int co = cog * 32 + c0;
        const ull* wr = (const ull*)(sw + co * 64);
        ull s2 = 0ull;
#pragma unroll
        for (int dd = 0; dd < 32; dd++)
            s2 = ffma2(a2[dd], wr[dd], s2);
        float s0, s1; upk2(s2, s0, s1);
        int oi = (b * 128 + co) * NQ + n;
        out[oi] += s0 + s1;
    }
}

// ---------------- launcher ---------------------------------------------------
extern "C" void kernel_launch(void* const* d_in, const int* in_sizes, int n_in,
                              void* d_out, int out_size)
{
    const float* x     = (const float*)d_in[0];
    const float* gamma = (const float*)d_in[1];
    const float* beta  = (const float*)d_in[2];
    const float* rmean = (const float*)d_in[3];
    const float* rvar  = (const float*)d_in[4];
    const float* w_sc  = (const float*)d_in[5];
    const float* w_q   = (const float*)d_in[6];
    const float* w_k   = (const float*)d_in[7];
    const float* w_v   = (const float*)d_in[8];
    const float* w_o   = (const float*)d_in[9];
    float* out = (float*)d_out;

    bn_kernel<<<4096, 256>>>(x, gamma, beta, rmean, rvar);
    repack_kernel<<<1728, 256>>>(w_sc, w_q);
    kv_kernel<<<dim3(32, 4), 256>>>(w_k, w_v);
    convt_kernel<<<dim3(65, 4, 2), 192>>>(out);
    attn_kernel<<<dim3(17, 8, 4), 256>>>();
    proj_kernel<<<dim3(67, 4), 256>>>(w_o, out);
}

// round 3
// speedup vs baseline: 1.3759x; 1.3759x over previous
#include <cuda_runtime.h>

// Problem constants
#define BB 4
#define CC 256
#define HWIN 1024      // 32*32
#define NQ 4225        // 65*65
#define NCO 192        // 128 shortcut + 64 q

typedef unsigned long long ull;

// ---------------- scratch (device globals) -----------------------------------
__device__ float g_xr[BB * CC * HWIN];        // BN+ReLU output [b][c][p]
__device__ float g_wt[CC * 9 * NCO];          // repacked conv weights [c][tap][co]
__device__ float g_q[BB * 64 * NQ];           // q conv output  [b][d][n]
__device__ float g_attO[BB * 64 * NQ];        // attention out  [b][d][n]
__device__ float g_kp[BB * 8 * 512 * 16];     // k pair-packed [b][h][j2][d(8)][2]
__device__ float g_vp[BB * 8 * 512 * 16];     // v pair-packed

// ---------------- f32x2 helpers ---------------------------------------------
__device__ __forceinline__ ull pk2(float a, float b) {
    ull r; asm("mov.b64 %0, {%1,%2};" : "=l"(r) : "f"(a), "f"(b)); return r;
}
__device__ __forceinline__ void upk2(ull v, float& a, float& b) {
    asm("mov.b64 {%0,%1}, %2;" : "=f"(a), "=f"(b) : "l"(v));
}
__device__ __forceinline__ ull ffma2(ull a, ull b, ull c) {
    ull r; asm("fma.rn.f32x2 %0, %1, %2, %3;" : "=l"(r) : "l"(a), "l"(b), "l"(c)); return r;
}
__device__ __forceinline__ ull fmul2(ull a, ull b) {
    ull r; asm("mul.rn.f32x2 %0, %1, %2;" : "=l"(r) : "l"(a), "l"(b)); return r;
}
__device__ __forceinline__ ull fadd2(ull a, ull b) {
    ull r; asm("add.rn.f32x2 %0, %1, %2;" : "=l"(r) : "l"(a), "l"(b)); return r;
}
__device__ __forceinline__ float ex2f(float x) {
    float r; asm("ex2.approx.f32 %0, %1;" : "=f"(r) : "f"(x)); return r;
}

// ---------------- kernel 1: BN (inference) + ReLU ----------------------------
__global__ void __launch_bounds__(256) bn_kernel(
    const float* __restrict__ x, const float* __restrict__ gamma,
    const float* __restrict__ beta, const float* __restrict__ rmean,
    const float* __restrict__ rvar)
{
    int idx = blockIdx.x * 256 + threadIdx.x;
    int c = (idx >> 10) & 255;
    float a = gamma[c] * rsqrtf(rvar[c] + 1e-5f);
    float bia = beta[c] - rmean[c] * a;
    g_xr[idx] = fmaxf(fmaf(x[idx], a, bia), 0.f);
}

// ---------------- kernel 2: repack + FLIP conv-transpose weights -------------
__global__ void __launch_bounds__(256) repack_kernel(
    const float* __restrict__ w_sc, const float* __restrict__ w_q)
{
    int i = blockIdx.x * 256 + threadIdx.x;            // [0, 442368)
    int c = i / (9 * NCO);
    int r = i - c * (9 * NCO);
    int t = r / NCO;
    int co = r - t * NCO;
    int s = 8 - t;   // spatial flip
    float v;
    if (co < 128) v = w_sc[(c * 128 + co) * 9 + s];
    else          v = w_q[(c * 64 + (co - 128)) * 9 + s];
    g_wt[i] = v;
}

// ---------------- kernel 3: k/v 1x1 projections, pair-packed -----------------
__global__ void __launch_bounds__(256) kv_kernel(
    const float* __restrict__ wk, const float* __restrict__ wv)
{
    const int b = blockIdx.y;
    const int p = blockIdx.x * 32 + (threadIdx.x & 31);
    const int dg = threadIdx.x >> 5;                   // 0..7
    const float* wbase = (dg < 4) ? (wk + dg * 16 * CC) : (wv + (dg - 4) * 16 * CC);
    const float* xp = g_xr + b * (CC * HWIN) + p;

    float acc[16];
#pragma unroll
    for (int i = 0; i < 16; i++) acc[i] = 0.f;

    for (int c = 0; c < CC; c += 4) {
        float x0 = xp[(c + 0) * HWIN];
        float x1 = xp[(c + 1) * HWIN];
        float x2 = xp[(c + 2) * HWIN];
        float x3 = xp[(c + 3) * HWIN];
#pragma unroll
        for (int i = 0; i < 16; i++) {
            float4 w4 = *(const float4*)(wbase + i * CC + c);
            acc[i] = fmaf(w4.x, x0, fmaf(w4.y, x1, fmaf(w4.z, x2, fmaf(w4.w, x3, acc[i]))));
        }
    }
    const int par = p & 1, j2 = p >> 1;
#pragma unroll
    for (int i = 0; i < 16; i++) {
        int d = dg * 16 + i;
        if (d < 64) {
            int hh = d >> 3, dd = d & 7;
            g_kp[(b * 8 + hh) * 8192 + j2 * 16 + dd * 2 + par] = acc[i];
        } else {
            int d2 = d - 64, hh = d2 >> 3, dd = d2 & 7;
            g_vp[(b * 8 + hh) * 8192 + j2 * 16 + dd * 2 + par] = acc[i];
        }
    }
}

// ---------------- kernel 4: fused ConvTranspose (R1 structure + prefetch) ----
template <int NJ>
__device__ __forceinline__ void load_row(float (&r)[NJ], const float* p, bool valid) {
    if (valid) {
        const float4* p4 = (const float4*)p;
#pragma unroll
        for (int q = 0; q < 4; q++) {
            float4 v = __ldg(p4 + q);
            r[4 * q + 0] = v.x; r[4 * q + 1] = v.y; r[4 * q + 2] = v.z; r[4 * q + 3] = v.w;
        }
        if (NJ == 17) r[16] = __ldg(p + 16);
    } else {
#pragma unroll
        for (int q = 0; q < NJ; q++) r[q] = 0.f;
    }
}

template <int XH>
__device__ __forceinline__ void conv_path(float* __restrict__ out, float* sAcc) {
    constexpr int NX = XH ? 32 : 33;
    constexpr int NJ = XH ? 16 : 17;
    constexpr int X0 = XH ? 33 : 0;
    constexpr int JB = XH ? 16 : 0;

    const int y = blockIdx.x;
    const int b = blockIdx.y;
    const int co = threadIdx.x;                        // 0..191
    const float* xrb = g_xr + b * (CC * HWIN);

    float acc[NX];
#pragma unroll
    for (int u = 0; u < NX; u++) acc[u] = 0.f;

    if ((y & 1) == 0) {
        const int iyA = y >> 1;        // flipped ky-tap 0
        const int iyB = iyA - 1;       // flipped ky-tap 2
        const bool vA = (iyA <= 31);
        const bool vB = (iyB >= 0);
        // prefetch c=0 weights
        const float* wp0 = g_wt + co;
        float wA0 = wp0[0];         float wA1 = wp0[NCO];     float wA2 = wp0[2 * NCO];
        float wB0 = wp0[6 * NCO];   float wB1 = wp0[7 * NCO]; float wB2 = wp0[8 * NCO];
        for (int c = 0; c < CC; c++) {
            // issue next-iteration weight loads first (covers L2 latency)
            const int cn = (c + 1 < CC) ? (c + 1) : c;
            const float* wq = g_wt + (cn * 9) * NCO + co;
            float nA0 = __ldg(wq);           float nA1 = __ldg(wq + NCO);
            float nA2 = __ldg(wq + 2 * NCO); float nB0 = __ldg(wq + 6 * NCO);
            float nB1 = __ldg(wq + 7 * NCO); float nB2 = __ldg(wq + 8 * NCO);

            float rA[NJ], rB[NJ];
            load_row<NJ>(rA, xrb + (c * 32 + iyA) * 32 + JB, vA);
            load_row<NJ>(rB, xrb + (c * 32 + iyB) * 32 + JB, vB);
#pragma unroll
            for (int u = 0; u < NX; u++) {
                const int x = X0 + u;
                if ((x & 1) == 0) {
                    const int jl = (x >> 1) - JB;
                    if (jl < NJ)  acc[u] += wA0 * rA[jl] + wB0 * rB[jl];
                    if (jl >= 1)  acc[u] += wA2 * rA[jl - 1] + wB2 * rB[jl - 1];
                } else {
                    const int jl = ((x - 1) >> 1) - JB;
                    acc[u] += wA1 * rA[jl] + wB1 * rB[jl];
                }
            }
            wA0 = nA0; wA1 = nA1; wA2 = nA2;
            wB0 = nB0; wB1 = nB1; wB2 = nB2;
        }
    } else {
        const int iyC = y >> 1;        // flipped ky-tap 1, always valid
        const float* wp0 = g_wt + co;
        float w0 = wp0[3 * NCO], w1 = wp0[4 * NCO], w2 = wp0[5 * NCO];
        for (int c = 0; c < CC; c++) {
            const int cn = (c + 1 < CC) ? (c + 1) : c;
            const float* wq = g_wt + (cn * 9) * NCO + co;
            float n0 = __ldg(wq + 3 * NCO);
            float n1 = __ldg(wq + 4 * NCO);
            float n2 = __ldg(wq + 5 * NCO);

            float rC[NJ];
            load_row<NJ>(rC, xrb + (c * 32 + iyC) * 32 + JB, true);
#pragma unroll
            for (int u = 0; u < NX; u++) {
                const int x = X0 + u;
                if ((x & 1) == 0) {
                    const int jl = (x >> 1) - JB;
                    if (jl < NJ)  acc[u] += w0 * rC[jl];
                    if (jl >= 1)  acc[u] += w2 * rC[jl - 1];
                } else {
                    const int jl = ((x - 1) >> 1) - JB;
                    acc[u] += w1 * rC[jl];
                }
            }
            w0 = n0; w1 = n1; w2 = n2;
        }
    }

    // smem transpose -> coalesced stores
#pragma unroll
    for (int u = 0; u < NX; u++) sAcc[co * 33 + u] = acc[u];
    __syncthreads();
    const int total = NCO * NX;
    for (int i = threadIdx.x; i < total; i += NCO) {
        int c2 = i / NX, u2 = i - c2 * NX;
        float v = sAcc[c2 * 33 + u2];
        int n = y * 65 + (X0 + u2);
        if (c2 < 128) out[(b * 128 + c2) * NQ + n] = v;
        else          g_q[(b * 64 + (c2 - 128)) * NQ + n] = v;
    }
}

__global__ void __launch_bounds__(192, 3) convt_kernel(float* __restrict__ out) {
    __shared__ float sAcc[NCO * 33];
    if (blockIdx.z == 0) conv_path<0>(out, sAcc);
    else                 conv_path<1>(out, sAcc);
}

// ---------------- kernel 5: attention, no-max softmax (scores bounded) -------
__global__ void __launch_bounds__(256) attn_kernel() {
    __shared__ float4 sk[1024];   // 256 key-pairs * 16 floats = 16KB
    __shared__ float4 sv[1024];
    const int qt = blockIdx.x, h = blockIdx.y, b = blockIdx.z;
    const int t = threadIdx.x;
    const int n = qt * 256 + t;
    const bool act = (n < NQ);

    // fold 1/sqrt(dk) * log2(e) into q
    const float sc = 0.35355339059327373f * 1.4426950408889634f;
    ull q2[8];
#pragma unroll
    for (int d = 0; d < 8; d++) {
        float qv = act ? g_q[(b * 64 + h * 8 + d) * NQ + n] * sc : 0.f;
        q2[d] = pk2(qv, qv);
    }
    ull l2 = 0ull;
    ull acc2[8];
#pragma unroll
    for (int d = 0; d < 8; d++) acc2[d] = 0ull;

    const float4* gk = (const float4*)(g_kp + (b * 8 + h) * 8192);
    const float4* gv = (const float4*)(g_vp + (b * 8 + h) * 8192);

    for (int ch = 0; ch < 2; ch++) {
        __syncthreads();
        for (int i = t; i < 1024; i += 256) {
            sk[i] = gk[ch * 1024 + i];
            sv[i] = gv[ch * 1024 + i];
        }
        __syncthreads();
        const ulonglong2* k2 = (const ulonglong2*)sk;
        const ulonglong2* v2 = (const ulonglong2*)sv;
        for (int j2 = 0; j2 < 256; j2++) {
            ulonglong2 ka = k2[j2 * 4 + 0];
            ulonglong2 kb = k2[j2 * 4 + 1];
            ulonglong2 kc = k2[j2 * 4 + 2];
            ulonglong2 kd = k2[j2 * 4 + 3];
            ull s2 = fmul2(q2[0], ka.x);
            s2 = ffma2(q2[1], ka.y, s2);
            s2 = ffma2(q2[2], kb.x, s2);
            s2 = ffma2(q2[3], kb.y, s2);
            s2 = ffma2(q2[4], kc.x, s2);
            s2 = ffma2(q2[5], kc.y, s2);
            s2 = ffma2(q2[6], kd.x, s2);
            s2 = ffma2(q2[7], kd.y, s2);
            float s0, s1; upk2(s2, s0, s1);
            float p0 = ex2f(s0);
            float p1 = ex2f(s1);
            ull p2 = pk2(p0, p1);
            l2 = fadd2(l2, p2);
            ulonglong2 va = v2[j2 * 4 + 0];
            ulonglong2 vb = v2[j2 * 4 + 1];
            ulonglong2 vc = v2[j2 * 4 + 2];
            ulonglong2 vd = v2[j2 * 4 + 3];
            acc2[0] = ffma2(p2, va.x, acc2[0]);
            acc2[1] = ffma2(p2, va.y, acc2[1]);
            acc2[2] = ffma2(p2, vb.x, acc2[2]);
            acc2[3] = ffma2(p2, vb.y, acc2[3]);
            acc2[4] = ffma2(p2, vc.x, acc2[4]);
            acc2[5] = ffma2(p2, vc.y, acc2[5]);
            acc2[6] = ffma2(p2, vd.x, acc2[6]);
            acc2[7] = ffma2(p2, vd.y, acc2[7]);
        }
    }
    if (act) {
        float l0, l1; upk2(l2, l0, l1);
        float inv = 1.f / (l0 + l1);
#pragma unroll
        for (int d = 0; d < 8; d++) {
            float a0, a1; upk2(acc2[d], a0, a1);
            g_attO[(b * 64 + h * 8 + d) * NQ + n] = (a0 + a1) * inv;
        }
    }
}

// ---------------- kernel 6: output projection + residual add (f32x2) ---------
__global__ void __launch_bounds__(256) proj_kernel(
    const float* __restrict__ w_o, float* __restrict__ out)
{
    __shared__ float sw[128 * 64];
    for (int i = threadIdx.x; i < 8192; i += 256) sw[i] = w_o[i];
    __syncthreads();

    const int b = blockIdx.y;
    const int nl = threadIdx.x & 63;
    const int cog = threadIdx.x >> 6;                  // 0..3 (32 co each)
    const int n = blockIdx.x * 64 + nl;
    if (n >= NQ) return;

    ull a2[32];
#pragma unroll
    for (int dd = 0; dd < 32; dd++) {
        float a0 = g_attO[(b * 64 + 2 * dd) * NQ + n];
        float a1 = g_attO[(b * 64 + 2 * dd + 1) * NQ + n];
        a2[dd] = pk2(a0, a1);
    }

    for (int c0 = 0; c0 < 32; c0++) {
        int co = cog * 32 + c0;
        const ull* wr = (const ull*)(sw + co * 64);
        ull s2 = 0ull;
#pragma unroll
        for (int dd = 0; dd < 32; dd++)
            s2 = ffma2(a2[dd], wr[dd], s2);
        float s0, s1; upk2(s2, s0, s1);
        int oi = (b * 128 + co) * NQ + n;
        out[oi] += s0 + s1;
    }
}

// ---------------- launcher ---------------------------------------------------
extern "C" void kernel_launch(void* const* d_in, const int* in_sizes, int n_in,
                              void* d_out, int out_size)
{
    const float* x     = (const float*)d_in[0];
    const float* gamma = (const float*)d_in[1];
    const float* beta  = (const float*)d_in[2];
    const float* rmean = (const float*)d_in[3];
    const float* rvar  = (const float*)d_in[4];
    const float* w_sc  = (const float*)d_in[5];
    const float* w_q   = (const float*)d_in[6];
    const float* w_k   = (const float*)d_in[7];
    const float* w_v   = (const float*)d_in[8];
    const float* w_o   = (const float*)d_in[9];
    float* out = (float*)d_out;

    bn_kernel<<<4096, 256>>>(x, gamma, beta, rmean, rvar);
    repack_kernel<<<1728, 256>>>(w_sc, w_q);
    kv_kernel<<<dim3(32, 4), 256>>>(w_k, w_v);
    convt_kernel<<<dim3(65, 4, 2), 192>>>(out);
    attn_kernel<<<dim3(17, 8, 4), 256>>>();
    proj_kernel<<<dim3(67, 4), 256>>>(w_o, out);
}

// round 4
// speedup vs baseline: 1.5008x; 1.0908x over previous
#include <cuda_runtime.h>

// Problem constants
#define BB 4
#define CC 256
#define HWIN 1024      // 32*32
#define NQ 4225        // 65*65
#define NCO 192        // 128 shortcut + 64 q

typedef unsigned long long ull;

// ---------------- scratch (device globals) -----------------------------------
__device__ float g_xr[BB * CC * HWIN];        // BN+ReLU output [b][c][p]
__device__ float g_wt[CC * 9 * NCO];          // repacked conv weights [c][tap][co]
__device__ float g_q[BB * 64 * NQ];           // q conv output  [b][d][n]
__device__ float g_attO[BB * 64 * NQ];        // attention out  [b][d][n]
__device__ float g_kp[BB * 8 * 512 * 16];     // k pair-packed [b][h][j2][d(8)][2]
__device__ float g_vp[BB * 8 * 512 * 16];     // v pair-packed

// ---------------- f32x2 helpers ---------------------------------------------
__device__ __forceinline__ ull pk2(float a, float b) {
    ull r; asm("mov.b64 %0, {%1,%2};" : "=l"(r) : "f"(a), "f"(b)); return r;
}
__device__ __forceinline__ void upk2(ull v, float& a, float& b) {
    asm("mov.b64 {%0,%1}, %2;" : "=f"(a), "=f"(b) : "l"(v));
}
__device__ __forceinline__ ull ffma2(ull a, ull b, ull c) {
    ull r; asm("fma.rn.f32x2 %0, %1, %2, %3;" : "=l"(r) : "l"(a), "l"(b), "l"(c)); return r;
}
__device__ __forceinline__ ull fmul2(ull a, ull b) {
    ull r; asm("mul.rn.f32x2 %0, %1, %2;" : "=l"(r) : "l"(a), "l"(b)); return r;
}
__device__ __forceinline__ ull fadd2(ull a, ull b) {
    ull r; asm("add.rn.f32x2 %0, %1, %2;" : "=l"(r) : "l"(a), "l"(b)); return r;
}
__device__ __forceinline__ float ex2f(float x) {
    float r; asm("ex2.approx.f32 %0, %1;" : "=f"(r) : "f"(x)); return r;
}

// ---------------- kernel 1: BN (inference) + ReLU ----------------------------
__global__ void __launch_bounds__(256) bn_kernel(
    const float* __restrict__ x, const float* __restrict__ gamma,
    const float* __restrict__ beta, const float* __restrict__ rmean,
    const float* __restrict__ rvar)
{
    int idx = blockIdx.x * 256 + threadIdx.x;
    int c = (idx >> 10) & 255;
    float a = gamma[c] * rsqrtf(rvar[c] + 1e-5f);
    float bia = beta[c] - rmean[c] * a;
    g_xr[idx] = fmaxf(fmaf(x[idx], a, bia), 0.f);
}

// ---------------- kernel 2: repack + FLIP conv-transpose weights -------------
__global__ void __launch_bounds__(256) repack_kernel(
    const float* __restrict__ w_sc, const float* __restrict__ w_q)
{
    int i = blockIdx.x * 256 + threadIdx.x;            // [0, 442368)
    int c = i / (9 * NCO);
    int r = i - c * (9 * NCO);
    int t = r / NCO;
    int co = r - t * NCO;
    int s = 8 - t;   // spatial flip
    float v;
    if (co < 128) v = w_sc[(c * 128 + co) * 9 + s];
    else          v = w_q[(c * 64 + (co - 128)) * 9 + s];
    g_wt[i] = v;
}

// ---------------- kernel 3: k/v 1x1 projections, pair-packed -----------------
__global__ void __launch_bounds__(256) kv_kernel(
    const float* __restrict__ wk, const float* __restrict__ wv)
{
    const int b = blockIdx.y;
    const int p = blockIdx.x * 32 + (threadIdx.x & 31);
    const int dg = threadIdx.x >> 5;                   // 0..7
    const float* wbase = (dg < 4) ? (wk + dg * 16 * CC) : (wv + (dg - 4) * 16 * CC);
    const float* xp = g_xr + b * (CC * HWIN) + p;

    float acc[16];
#pragma unroll
    for (int i = 0; i < 16; i++) acc[i] = 0.f;

    for (int c = 0; c < CC; c += 4) {
        float x0 = xp[(c + 0) * HWIN];
        float x1 = xp[(c + 1) * HWIN];
        float x2 = xp[(c + 2) * HWIN];
        float x3 = xp[(c + 3) * HWIN];
#pragma unroll
        for (int i = 0; i < 16; i++) {
            float4 w4 = *(const float4*)(wbase + i * CC + c);
            acc[i] = fmaf(w4.x, x0, fmaf(w4.y, x1, fmaf(w4.z, x2, fmaf(w4.w, x3, acc[i]))));
        }
    }
    const int par = p & 1, j2 = p >> 1;
#pragma unroll
    for (int i = 0; i < 16; i++) {
        int d = dg * 16 + i;
        if (d < 64) {
            int hh = d >> 3, dd = d & 7;
            g_kp[(b * 8 + hh) * 8192 + j2 * 16 + dd * 2 + par] = acc[i];
        } else {
            int d2 = d - 64, hh = d2 >> 3, dd = d2 & 7;
            g_vp[(b * 8 + hh) * 8192 + j2 * 16 + dd * 2 + par] = acc[i];
        }
    }
}

// ---------------- kernel 4: ConvTranspose, co-pair f32x2, 2-pass tap rows ----
// Thread = one co-pair (co,co+1) x one x-quarter. Weight pairs via LDG.64
// (co-contiguous), row values packed once and reused by all taps.
template <int XH, int Q, int NP>
__device__ __forceinline__ void conv_body(float* sAcc) {
    constexpr int x0    = (XH == 0) ? (Q ? 17 : 0) : (Q ? 49 : 33);
    constexpr int jbase = 8 * (2 * XH + Q);
    constexpr bool has9 = !(XH == 1 && Q == 1);
    constexpr int uoff  = (XH == 0) ? (Q ? 17 : 0) : (Q ? 16 : 0);

    const int y = blockIdx.x;
    const int b = blockIdx.y;
    const int cp = threadIdx.x % 96;
    const int co = cp * 2;
    const float* xrb = g_xr + b * (CC * HWIN);

    ull acc[NP];
#pragma unroll
    for (int u = 0; u < NP; u++) acc[u] = 0ull;

    // one pass over c for a single (input row line, tap row) combination
    auto pass = [&](int iy, int tb) {
        const float* rowp = xrb + iy * 32 + jbase;
        const ull* wp = (const ull*)(g_wt + tb * NCO + co);
        ull w0 = __ldg(wp);
        ull w1 = __ldg(wp + NCO / 2);
        ull w2 = __ldg(wp + NCO);
        for (int c = 0; c < CC; c++) {
            const int cn = (c + 1 < CC) ? (c + 1) : c;
            const ull* wn = (const ull*)(g_wt + (cn * 9 + tb) * NCO + co);
            ull n0 = __ldg(wn);
            ull n1 = __ldg(wn + NCO / 2);
            ull n2 = __ldg(wn + NCO);

            const float* rp = rowp + c * HWIN;
            float4 ra = __ldg((const float4*)rp);
            float4 rb = __ldg((const float4*)(rp + 4));
            ull P[9];
            P[0] = pk2(ra.x, ra.x); P[1] = pk2(ra.y, ra.y);
            P[2] = pk2(ra.z, ra.z); P[3] = pk2(ra.w, ra.w);
            P[4] = pk2(rb.x, rb.x); P[5] = pk2(rb.y, rb.y);
            P[6] = pk2(rb.z, rb.z); P[7] = pk2(rb.w, rb.w);
            if (has9) { float r8 = __ldg(rp + 8); P[8] = pk2(r8, r8); }
            else       P[8] = 0ull;

#pragma unroll
            for (int u = 0; u < NP; u++) {
                const int x = x0 + u;
                if ((x & 1) == 0) {
                    const int jl = (x >> 1) - jbase;
                    acc[u] = ffma2(w0, P[jl], acc[u]);
                    if (jl >= 1) acc[u] = ffma2(w2, P[jl - 1], acc[u]);
                } else {
                    const int jl = ((x - 1) >> 1) - jbase;
                    acc[u] = ffma2(w1, P[jl], acc[u]);
                }
            }
            w0 = n0; w1 = n1; w2 = n2;
        }
    };

    if ((y & 1) == 0) {
        const int iyA = y >> 1;          // flipped ky-tap row 0
        const int iyB = iyA - 1;         // flipped ky-tap row 2
        if (iyA <= 31) pass(iyA, 0);
        if (iyB >= 0)  pass(iyB, 6);
    } else {
        pass(y >> 1, 3);                 // flipped ky-tap row 1
    }

#pragma unroll
    for (int u = 0; u < NP; u++) {
        float a0, a1; upk2(acc[u], a0, a1);
        sAcc[co * 33 + uoff + u]       = a0;
        sAcc[(co + 1) * 33 + uoff + u] = a1;
    }
}

__global__ void __launch_bounds__(192, 4) convt_kernel(float* __restrict__ out) {
    __shared__ float sAcc[NCO * 33];
    const int XH = blockIdx.z;
    const int q = threadIdx.x / 96;      // warps 0-2: q=0, warps 3-5: q=1
    if (XH == 0) {
        if (q == 0) conv_body<0, 0, 17>(sAcc);
        else        conv_body<0, 1, 16>(sAcc);
    } else {
        if (q == 0) conv_body<1, 0, 16>(sAcc);
        else        conv_body<1, 1, 16>(sAcc);
    }
    __syncthreads();

    const int NXh = (XH == 0) ? 33 : 32;
    const int X0h = (XH == 0) ? 0 : 33;
    const int b = blockIdx.y;
    const int total = NCO * NXh;
    for (int i = threadIdx.x; i < total; i += 192) {
        int c2 = i / NXh, u2 = i - c2 * NXh;
        float v = sAcc[c2 * 33 + u2];
        int n = blockIdx.x * 65 + X0h + u2;
        if (c2 < 128) out[(b * 128 + c2) * NQ + n] = v;
        else          g_q[(b * 64 + (c2 - 128)) * NQ + n] = v;
    }
}

// ---------------- kernel 5: attention, no-max softmax (scores bounded) -------
__global__ void __launch_bounds__(256) attn_kernel() {
    __shared__ float4 sk[1024];   // 256 key-pairs * 16 floats = 16KB
    __shared__ float4 sv[1024];
    const int qt = blockIdx.x, h = blockIdx.y, b = blockIdx.z;
    const int t = threadIdx.x;
    const int n = qt * 256 + t;
    const bool act = (n < NQ);

    // fold 1/sqrt(dk) * log2(e) into q
    const float sc = 0.35355339059327373f * 1.4426950408889634f;
    ull q2[8];
#pragma unroll
    for (int d = 0; d < 8; d++) {
        float qv = act ? g_q[(b * 64 + h * 8 + d) * NQ + n] * sc : 0.f;
        q2[d] = pk2(qv, qv);
    }
    ull l2 = 0ull;
    ull acc2[8];
#pragma unroll
    for (int d = 0; d < 8; d++) acc2[d] = 0ull;

    const float4* gk = (const float4*)(g_kp + (b * 8 + h) * 8192);
    const float4* gv = (const float4*)(g_vp + (b * 8 + h) * 8192);

    for (int ch = 0; ch < 2; ch++) {
        __syncthreads();
        for (int i = t; i < 1024; i += 256) {
            sk[i] = gk[ch * 1024 + i];
            sv[i] = gv[ch * 1024 + i];
        }
        __syncthreads();
        const ulonglong2* k2 = (const ulonglong2*)sk;
        const ulonglong2* v2 = (const ulonglong2*)sv;
        for (int j2 = 0; j2 < 256; j2++) {
            ulonglong2 ka = k2[j2 * 4 + 0];
            ulonglong2 kb = k2[j2 * 4 + 1];
            ulonglong2 kc = k2[j2 * 4 + 2];
            ulonglong2 kd = k2[j2 * 4 + 3];
            ull s2 = fmul2(q2[0], ka.x);
            s2 = ffma2(q2[1], ka.y, s2);
            s2 = ffma2(q2[2], kb.x, s2);
            s2 = ffma2(q2[3], kb.y, s2);
            s2 = ffma2(q2[4], kc.x, s2);
            s2 = ffma2(q2[5], kc.y, s2);
            s2 = ffma2(q2[6], kd.x, s2);
            s2 = ffma2(q2[7], kd.y, s2);
            float s0, s1; upk2(s2, s0, s1);
            float p0 = ex2f(s0);
            float p1 = ex2f(s1);
            ull p2 = pk2(p0, p1);
            l2 = fadd2(l2, p2);
            ulonglong2 va = v2[j2 * 4 + 0];
            ulonglong2 vb = v2[j2 * 4 + 1];
            ulonglong2 vc = v2[j2 * 4 + 2];
            ulonglong2 vd = v2[j2 * 4 + 3];
            acc2[0] = ffma2(p2, va.x, acc2[0]);
            acc2[1] = ffma2(p2, va.y, acc2[1]);
            acc2[2] = ffma2(p2, vb.x, acc2[2]);
            acc2[3] = ffma2(p2, vb.y, acc2[3]);
            acc2[4] = ffma2(p2, vc.x, acc2[4]);
            acc2[5] = ffma2(p2, vc.y, acc2[5]);
            acc2[6] = ffma2(p2, vd.x, acc2[6]);
            acc2[7] = ffma2(p2, vd.y, acc2[7]);
        }
    }
    if (act) {
        float l0, l1; upk2(l2, l0, l1);
        float inv = 1.f / (l0 + l1);
#pragma unroll
        for (int d = 0; d < 8; d++) {
            float a0, a1; upk2(acc2[d], a0, a1);
            g_attO[(b * 64 + h * 8 + d) * NQ + n] = (a0 + a1) * inv;
        }
    }
}

// ---------------- kernel 6: output projection + residual add (f32x2) ---------
__global__ void __launch_bounds__(256) proj_kernel(
    const float* __restrict__ w_o, float* __restrict__ out)
{
    __shared__ float sw[128 * 64];
    for (int i = threadIdx.x; i < 8192; i += 256) sw[i] = w_o[i];
    __syncthreads();

    const int b = blockIdx.y;
    const int nl = threadIdx.x & 63;
    const int cog = threadIdx.x >> 6;                  // 0..3 (32 co each)
    const int n = blockIdx.x * 64 + nl;
    if (n >= NQ) return;

    ull a2[32];
#pragma unroll
    for (int dd = 0; dd < 32; dd++) {
        float a0 = g_attO[(b * 64 + 2 * dd) * NQ + n];
        float a1 = g_attO[(b * 64 + 2 * dd + 1) * NQ + n];
        a2[dd] = pk2(a0, a1);
    }

    for (int c0 = 0; c0 < 32; c0++) {
        int co = cog * 32 + c0;
        const ull* wr = (const ull*)(sw + co * 64);
        ull s2 = 0ull;
#pragma unroll
        for (int dd = 0; dd < 32; dd++)
            s2 = ffma2(a2[dd], wr[dd], s2);
        float s0, s1; upk2(s2, s0, s1);
        int oi = (b * 128 + co) * NQ + n;
        out[oi] += s0 + s1;
    }
}

// ---------------- launcher ---------------------------------------------------
extern "C" void kernel_launch(void* const* d_in, const int* in_sizes, int n_in,
                              void* d_out, int out_size)
{
    const float* x     = (const float*)d_in[0];
    const float* gamma = (const float*)d_in[1];
    const float* beta  = (const float*)d_in[2];
    const float* rmean = (const float*)d_in[3];
    const float* rvar  = (const float*)d_in[4];
    const float* w_sc  = (const float*)d_in[5];
    const float* w_q   = (const float*)d_in[6];
    const float* w_k   = (const float*)d_in[7];
    const float* w_v   = (const float*)d_in[8];
    const float* w_o   = (const float*)d_in[9];
    float* out = (float*)d_out;

    bn_kernel<<<4096, 256>>>(x, gamma, beta, rmean, rvar);
    repack_kernel<<<1728, 256>>>(w_sc, w_q);
    kv_kernel<<<dim3(32, 4), 256>>>(w_k, w_v);
    convt_kernel<<<dim3(65, 4, 2), 192>>>(out);
    attn_kernel<<<dim3(17, 8, 4), 256>>>();
    proj_kernel<<<dim3(67, 4), 256>>>(w_o, out);
}

// round 7
// speedup vs baseline: 1.9764x; 1.3169x over previous
#include <cuda_runtime.h>
#include <cstdint>

#define BB 4
#define CC 256
#define NQ 4225        // 65*65
#define NCO 192        // 128 shortcut + 64 q
#define MPAD 1792      // 9*192=1728 padded to 14*128
#define NTOT 4096      // 4 b * 1024 p

typedef unsigned long long ull;

// ---------------- scratch (device globals; no allocation allowed) ------------
__device__ float g_xrT[BB * 1024 * CC];       // BN+ReLU, transposed [b][p][c] (tf32-rounded)
__device__ float g_wA[MPAD * CC];             // GEMM A: [m=t*192+co][c] (flipped taps, tf32)
__device__ float g_Y[MPAD * NTOT];            // GEMM result [m][n=b*1024+p]
__device__ float g_q[BB * 64 * NQ];           // q conv output  [b][d][n]
__device__ float g_attO[BB * 64 * NQ];        // attention out  [b][d][n]
__device__ float g_kp[BB * 8 * 512 * 16];     // k pair-packed [b][h][j2][d(8)][2]
__device__ float g_vp[BB * 8 * 512 * 16];     // v pair-packed

// ---------------- helpers ----------------------------------------------------
__device__ __forceinline__ ull pk2(float a, float b) {
    ull r; asm("mov.b64 %0, {%1,%2};" : "=l"(r) : "f"(a), "f"(b)); return r;
}
__device__ __forceinline__ void upk2(ull v, float& a, float& b) {
    asm("mov.b64 {%0,%1}, %2;" : "=f"(a), "=f"(b) : "l"(v));
}
__device__ __forceinline__ ull ffma2(ull a, ull b, ull c) {
    ull r; asm("fma.rn.f32x2 %0, %1, %2, %3;" : "=l"(r) : "l"(a), "l"(b), "l"(c)); return r;
}
__device__ __forceinline__ ull fmul2(ull a, ull b) {
    ull r; asm("mul.rn.f32x2 %0, %1, %2;" : "=l"(r) : "l"(a), "l"(b)); return r;
}
__device__ __forceinline__ ull fadd2(ull a, ull b) {
    ull r; asm("add.rn.f32x2 %0, %1, %2;" : "=l"(r) : "l"(a), "l"(b)); return r;
}
__device__ __forceinline__ float ex2f(float x) {
    float r; asm("ex2.approx.f32 %0, %1;" : "=f"(r) : "f"(x)); return r;
}
__device__ __forceinline__ float tf32r(float x) {   // round-to-nearest tf32
    float r; asm("cvt.rna.tf32.f32 %0, %1;" : "=f"(r) : "f"(x)); return r;
}

// mma.sync m16n8k8 tf32 (baseline PTX, works on compute_103)
__device__ __forceinline__ void mma16n8k8(float* d, const uint32_t* a, const uint32_t* b) {
    asm volatile(
        "mma.sync.aligned.m16n8k8.row.col.f32.tf32.tf32.f32 "
        "{%0,%1,%2,%3}, {%4,%5,%6,%7}, {%8,%9}, {%0,%1,%2,%3};"
        : "+f"(d[0]), "+f"(d[1]), "+f"(d[2]), "+f"(d[3])
        : "r"(a[0]), "r"(a[1]), "r"(a[2]), "r"(a[3]), "r"(b[0]), "r"(b[1]));
}

// ---------------- kernel 1: BN + ReLU + transpose -> xrT[b][p][c] (tf32) -----
__global__ void __launch_bounds__(256) bnT_kernel(
    const float* __restrict__ x, const float* __restrict__ gamma,
    const float* __restrict__ beta, const float* __restrict__ rmean,
    const float* __restrict__ rvar)
{
    __shared__ float s[32][33];
    const int pb = blockIdx.x, cb = blockIdx.y, b = blockIdx.z;
    const int tx = threadIdx.x, ty = threadIdx.y;     // 32 x 8
#pragma unroll
    for (int k = 0; k < 4; k++) {
        int cl = ty + k * 8;
        int c = cb * 32 + cl;
        float a = gamma[c] * rsqrtf(rvar[c] + 1e-5f);
        float bia = beta[c] - rmean[c] * a;
        float v = fmaxf(fmaf(x[(b * 256 + c) * 1024 + pb * 32 + tx], a, bia), 0.f);
        s[cl][tx] = v;
    }
    __syncthreads();
#pragma unroll
    for (int k = 0; k < 4; k++) {
        int pl = ty + k * 8;
        int p = pb * 32 + pl;
        g_xrT[(b * 1024 + p) * 256 + cb * 32 + tx] = tf32r(s[tx][pl]);
    }
}

// ---------------- kernel 2: pack A = [m=t*192+co][c], flipped taps, tf32 -----
__global__ void __launch_bounds__(256) wpack_kernel(
    const float* __restrict__ w_sc, const float* __restrict__ w_q)
{
    int i = blockIdx.x * 256 + threadIdx.x;           // [0, 1792*256)
    int m = i >> 8, c = i & 255;
    float v = 0.f;
    if (m < 1728) {
        int t = m / NCO, co = m - t * NCO;
        int s = 8 - t;                                 // spatial flip (verified in R1)
        if (co < 128) v = w_sc[(c * 128 + co) * 9 + s];
        else          v = w_q[(c * 64 + (co - 128)) * 9 + s];
    }
    g_wA[i] = tf32r(v);
}

// ---------------- kernel 3: k/v 1x1 projections from xrT, pair-packed --------
__global__ void __launch_bounds__(256) kv_kernel(
    const float* __restrict__ wk, const float* __restrict__ wv)
{
    const int b = blockIdx.y;
    const int p = blockIdx.x * 32 + (threadIdx.x & 31);
    const int dg = threadIdx.x >> 5;                  // 0..7
    const float* wbase = (dg < 4) ? (wk + dg * 16 * CC) : (wv + (dg - 4) * 16 * CC);
    const float* xp = g_xrT + (b * 1024 + p) * 256;

    float acc[16];
#pragma unroll
    for (int i = 0; i < 16; i++) acc[i] = 0.f;

    for (int c = 0; c < CC; c += 4) {
        float4 xv = *(const float4*)(xp + c);
#pragma unroll
        for (int i = 0; i < 16; i++) {
            float4 w4 = *(const float4*)(wbase + i * CC + c);
            acc[i] = fmaf(w4.x, xv.x, fmaf(w4.y, xv.y, fmaf(w4.z, xv.z, fmaf(w4.w, xv.w, acc[i]))));
        }
    }
    const int par = p & 1, j2 = p >> 1;
#pragma unroll
    for (int i = 0; i < 16; i++) {
        int d = dg * 16 + i;
        if (d < 64) {
            int hh = d >> 3, dd = d & 7;
            g_kp[(b * 8 + hh) * 8192 + j2 * 16 + dd * 2 + par] = acc[i];
        } else {
            int d2 = d - 64, hh = d2 >> 3, dd = d2 & 7;
            g_vp[(b * 8 + hh) * 8192 + j2 * 16 + dd * 2 + par] = acc[i];
        }
    }
}

// ---------------- kernel 4: warp-MMA tf32 GEMM  Y = W_all x X^T --------------
// Block 128x128, 8 warps (2m x 4n), warp = 64x32 via 4x4 m16n8k8 tiles.
// K=256 in 8 chunks of 32. smem stride 36 floats => conflict-free frag loads.
// A-fragment order (PTX): a0=(g,tg) a1=(g+8,tg) a2=(g,tg+4) a3=(g+8,tg+4).
#define SSTR 36
__global__ void __launch_bounds__(256) gemm_kernel() {
    __shared__ __align__(16) float As[128 * SSTR];
    __shared__ __align__(16) float Bs[128 * SSTR];
    const int tid = threadIdx.x;
    const int wid = tid >> 5, lane = tid & 31;
    const int nt = blockIdx.x, mt = blockIdx.y;
    const int wm = wid & 1, wn = wid >> 1;            // 2 x 4
    const int g = lane >> 2, tg = lane & 3;

    float acc[4][4][4];
#pragma unroll
    for (int mi = 0; mi < 4; mi++)
#pragma unroll
        for (int ni = 0; ni < 4; ni++)
#pragma unroll
            for (int q = 0; q < 4; q++) acc[mi][ni][q] = 0.f;

    for (int kc = 0; kc < 8; kc++) {
#pragma unroll
        for (int i = 0; i < 4; i++) {
            int fl = i * 256 + tid;                    // float4 idx, 8 per row
            int row = fl >> 3, k4 = fl & 7;
            float4 va = *(const float4*)(g_wA + (size_t)(mt * 128 + row) * 256 + kc * 32 + k4 * 4);
            *(float4*)&As[row * SSTR + k4 * 4] = va;
            float4 vb = *(const float4*)(g_xrT + (size_t)(nt * 128 + row) * 256 + kc * 32 + k4 * 4);
            *(float4*)&Bs[row * SSTR + k4 * 4] = vb;
        }
        __syncthreads();

#pragma unroll
        for (int ks = 0; ks < 4; ks++) {
            uint32_t a[4][4], b[4][2];
#pragma unroll
            for (int mi = 0; mi < 4; mi++) {
                const float* ap = &As[(wm * 64 + mi * 16) * SSTR + ks * 8];
                a[mi][0] = __float_as_uint(ap[g * SSTR + tg]);
                a[mi][1] = __float_as_uint(ap[(g + 8) * SSTR + tg]);
                a[mi][2] = __float_as_uint(ap[g * SSTR + tg + 4]);
                a[mi][3] = __float_as_uint(ap[(g + 8) * SSTR + tg + 4]);
            }
#pragma unroll
            for (int ni = 0; ni < 4; ni++) {
                const float* bp = &Bs[(wn * 32 + ni * 8) * SSTR + ks * 8];
                b[ni][0] = __float_as_uint(bp[g * SSTR + tg]);
                b[ni][1] = __float_as_uint(bp[g * SSTR + tg + 4]);
            }
#pragma unroll
            for (int mi = 0; mi < 4; mi++)
#pragma unroll
                for (int ni = 0; ni < 4; ni++)
                    mma16n8k8(acc[mi][ni], a[mi], b[ni]);
        }
        __syncthreads();
    }

    // epilogue: float2 stores to g_Y  (c0/c1 row g; c2/c3 row g+8)
#pragma unroll
    for (int mi = 0; mi < 4; mi++) {
#pragma unroll
        for (int ni = 0; ni < 4; ni++) {
            int row0 = mt * 128 + wm * 64 + mi * 16 + g;
            int col  = nt * 128 + wn * 32 + ni * 8 + 2 * tg;
            float2 v0 = make_float2(acc[mi][ni][0], acc[mi][ni][1]);
            float2 v1 = make_float2(acc[mi][ni][2], acc[mi][ni][3]);
            *(float2*)(g_Y + (size_t)row0 * NTOT + col) = v0;
            *(float2*)(g_Y + (size_t)(row0 + 8) * NTOT + col) = v1;
        }
    }
}

// ---------------- kernel 5: tap-gather  Y -> out(shortcut) + g_q -------------
__global__ void __launch_bounds__(256) gather_kernel(float* __restrict__ out) {
    const int y = blockIdx.x, b = blockIdx.y;

    int tys[2], iys[2], nyy = 0;
    if (y & 1) { tys[0] = 1; iys[0] = y >> 1; nyy = 1; }
    else {
        if ((y >> 1) <= 31)    { tys[nyy] = 0; iys[nyy] = y >> 1;       nyy++; }
        if ((y >> 1) - 1 >= 0) { tys[nyy] = 2; iys[nyy] = (y >> 1) - 1; nyy++; }
    }

    for (int idx = threadIdx.x; idx < NCO * 65; idx += 256) {
        int co = idx / 65;
        int x = idx - co * 65;
        int txs[2], ixs[2], nxx = 0;
        if (x & 1) { txs[0] = 1; ixs[0] = x >> 1; nxx = 1; }
        else {
            if ((x >> 1) <= 31)    { txs[nxx] = 0; ixs[nxx] = x >> 1;       nxx++; }
            if ((x >> 1) - 1 >= 0) { txs[nxx] = 2; ixs[nxx] = (x >> 1) - 1; nxx++; }
        }
        float s = 0.f;
        for (int yi = 0; yi < nyy; yi++)
            for (int xi = 0; xi < nxx; xi++) {
                int t = tys[yi] * 3 + txs[xi];
                s += g_Y[(size_t)(t * NCO + co) * NTOT + b * 1024 + iys[yi] * 32 + ixs[xi]];
            }
        int n = y * 65 + x;
        if (co < 128) out[(b * 128 + co) * NQ + n] = s;
        else          g_q[(b * 64 + (co - 128)) * NQ + n] = s;
    }
}

// ---------------- kernel 6: attention (unchanged) ----------------------------
__global__ void __launch_bounds__(256) attn_kernel() {
    __shared__ float4 sk[1024];
    __shared__ float4 sv[1024];
    const int qt = blockIdx.x, h = blockIdx.y, b = blockIdx.z;
    const int t = threadIdx.x;
    const int n = qt * 256 + t;
    const bool act = (n < NQ);

    const float sc = 0.35355339059327373f * 1.4426950408889634f;
    ull q2[8];
#pragma unroll
    for (int d = 0; d < 8; d++) {
        float qv = act ? g_q[(b * 64 + h * 8 + d) * NQ + n] * sc : 0.f;
        q2[d] = pk2(qv, qv);
    }
    ull l2 = 0ull;
    ull acc2[8];
#pragma unroll
    for (int d = 0; d < 8; d++) acc2[d] = 0ull;

    const float4* gk = (const float4*)(g_kp + (b * 8 + h) * 8192);
    const float4* gv = (const float4*)(g_vp + (b * 8 + h) * 8192);

    for (int ch = 0; ch < 2; ch++) {
        __syncthreads();
        for (int i = t; i < 1024; i += 256) {
            sk[i] = gk[ch * 1024 + i];
            sv[i] = gv[ch * 1024 + i];
        }
        __syncthreads();
        const ulonglong2* k2 = (const ulonglong2*)sk;
        const ulonglong2* v2 = (const ulonglong2*)sv;
        for (int j2 = 0; j2 < 256; j2++) {
            ulonglong2 ka = k2[j2 * 4 + 0];
            ulonglong2 kb = k2[j2 * 4 + 1];
            ulonglong2 kc = k2[j2 * 4 + 2];
            ulonglong2 kd = k2[j2 * 4 + 3];
            ull s2 = fmul2(q2[0], ka.x);
            s2 = ffma2(q2[1], ka.y, s2);
            s2 = ffma2(q2[2], kb.x, s2);
            s2 = ffma2(q2[3], kb.y, s2);
            s2 = ffma2(q2[4], kc.x, s2);
            s2 = ffma2(q2[5], kc.y, s2);
            s2 = ffma2(q2[6], kd.x, s2);
            s2 = ffma2(q2[7], kd.y, s2);
            float s0, s1; upk2(s2, s0, s1);
            float p0 = ex2f(s0);
            float p1 = ex2f(s1);
            ull p2 = pk2(p0, p1);
            l2 = fadd2(l2, p2);
            ulonglong2 va = v2[j2 * 4 + 0];
            ulonglong2 vb = v2[j2 * 4 + 1];
            ulonglong2 vc = v2[j2 * 4 + 2];
            ulonglong2 vd = v2[j2 * 4 + 3];
            acc2[0] = ffma2(p2, va.x, acc2[0]);
            acc2[1] = ffma2(p2, va.y, acc2[1]);
            acc2[2] = ffma2(p2, vb.x, acc2[2]);
            acc2[3] = ffma2(p2, vb.y, acc2[3]);
            acc2[4] = ffma2(p2, vc.x, acc2[4]);
            acc2[5] = ffma2(p2, vc.y, acc2[5]);
            acc2[6] = ffma2(p2, vd.x, acc2[6]);
            acc2[7] = ffma2(p2, vd.y, acc2[7]);
        }
    }
    if (act) {
        float l0, l1; upk2(l2, l0, l1);
        float inv = 1.f / (l0 + l1);
#pragma unroll
        for (int d = 0; d < 8; d++) {
            float a0, a1; upk2(acc2[d], a0, a1);
            g_attO[(b * 64 + h * 8 + d) * NQ + n] = (a0 + a1) * inv;
        }
    }
}

// ---------------- kernel 7: output projection + residual add -----------------
__global__ void __launch_bounds__(256) proj_kernel(
    const float* __restrict__ w_o, float* __restrict__ out)
{
    __shared__ float sw[128 * 64];
    for (int i = threadIdx.x; i < 8192; i += 256) sw[i] = w_o[i];
    __syncthreads();

    const int b = blockIdx.y;
    const int nl = threadIdx.x & 63;
    const int cog = threadIdx.x >> 6;
    const int n = blockIdx.x * 64 + nl;
    if (n >= NQ) return;

    ull a2[32];
#pragma unroll
    for (int dd = 0; dd < 32; dd++) {
        float a0 = g_attO[(b * 64 + 2 * dd) * NQ + n];
        float a1 = g_attO[(b * 64 + 2 * dd + 1) * NQ + n];
        a2[dd] = pk2(a0, a1);
    }

    for (int c0 = 0; c0 < 32; c0++) {
        int co = cog * 32 + c0;
        const ull* wr = (const ull*)(sw + co * 64);
        ull s2 = 0ull;
#pragma unroll
        for (int dd = 0; dd < 32; dd++)
            s2 = ffma2(a2[dd], wr[dd], s2);
        float s0, s1; upk2(s2, s0, s1);
        int oi = (b * 128 + co) * NQ + n;
        out[oi] += s0 + s1;
    }
}

// ---------------- launcher ---------------------------------------------------
extern "C" void kernel_launch(void* const* d_in, const int* in_sizes, int n_in,
                              void* d_out, int out_size)
{
    const float* x     = (const float*)d_in[0];
    const float* gamma = (const float*)d_in[1];
    const float* beta  = (const float*)d_in[2];
    const float* rmean = (const float*)d_in[3];
    const float* rvar  = (const float*)d_in[4];
    const float* w_sc  = (const float*)d_in[5];
    const float* w_q   = (const float*)d_in[6];
    const float* w_k   = (const float*)d_in[7];
    const float* w_v   = (const float*)d_in[8];
    const float* w_o   = (const float*)d_in[9];
    float* out = (float*)d_out;

    bnT_kernel<<<dim3(32, 8, 4), dim3(32, 8)>>>(x, gamma, beta, rmean, rvar);
    wpack_kernel<<<1792, 256>>>(w_sc, w_q);
    kv_kernel<<<dim3(32, 4), 256>>>(w_k, w_v);
    gemm_kernel<<<dim3(32, 14), 256>>>();
    gather_kernel<<<dim3(65, 4), 256>>>(out);
    attn_kernel<<<dim3(17, 8, 4), 256>>>();
    proj_kernel<<<dim3(67, 4), 256>>>(w_o, out);
}

// round 8
// speedup vs baseline: 2.9140x; 1.4744x over previous
#include <cuda_runtime.h>
#include <cstdint>

#define BB 4
#define CC 256
#define NQ 4225        // 65*65
#define NCO 192        // 128 shortcut + 64 q
#define MPAD 1920      // 1728 conv + 64 k + 64 v, padded to 15*128
#define NTOT 4096      // 4 b * 1024 p

typedef unsigned long long ull;

// ---------------- scratch (device globals; no allocation allowed) ------------
__device__ float g_xrT[BB * 1024 * CC];       // BN+ReLU, transposed [b][p][c] (tf32-rounded)
__device__ float g_wA[MPAD * CC];             // GEMM A rows: conv taps (flipped) + wk + wv
__device__ float g_Y[MPAD * NTOT];            // GEMM result [m][n=b*1024+p]
__device__ float g_q[BB * 64 * NQ];           // q conv output  [b][d][n]
__device__ float g_attO[BB * 64 * NQ];        // attention out  [b][d][n]

// ---------------- helpers ----------------------------------------------------
__device__ __forceinline__ ull pk2(float a, float b) {
    ull r; asm("mov.b64 %0, {%1,%2};" : "=l"(r) : "f"(a), "f"(b)); return r;
}
__device__ __forceinline__ void upk2(ull v, float& a, float& b) {
    asm("mov.b64 {%0,%1}, %2;" : "=f"(a), "=f"(b) : "l"(v));
}
__device__ __forceinline__ ull ffma2(ull a, ull b, ull c) {
    ull r; asm("fma.rn.f32x2 %0, %1, %2, %3;" : "=l"(r) : "l"(a), "l"(b), "l"(c)); return r;
}
__device__ __forceinline__ float ex2f(float x) {
    float r; asm("ex2.approx.f32 %0, %1;" : "=f"(r) : "f"(x)); return r;
}
__device__ __forceinline__ float tf32r(float x) {   // round-to-nearest tf32
    float r; asm("cvt.rna.tf32.f32 %0, %1;" : "=f"(r) : "f"(x)); return r;
}

// mma.sync m16n8k8 tf32. Frag layouts (PTX, verified R7):
//  A: a0=(g,tg) a1=(g+8,tg) a2=(g,tg+4) a3=(g+8,tg+4)
//  B: b0=(k=tg, n=g) b1=(k=tg+4, n=g)
//  C: c0=(g,2tg) c1=(g,2tg+1) c2=(g+8,2tg) c3=(g+8,2tg+1)
__device__ __forceinline__ void mma_acc(float* d, const uint32_t* a, uint32_t b0, uint32_t b1) {
    asm volatile(
        "mma.sync.aligned.m16n8k8.row.col.f32.tf32.tf32.f32 "
        "{%0,%1,%2,%3}, {%4,%5,%6,%7}, {%8,%9}, {%0,%1,%2,%3};"
        : "+f"(d[0]), "+f"(d[1]), "+f"(d[2]), "+f"(d[3])
        : "r"(a[0]), "r"(a[1]), "r"(a[2]), "r"(a[3]), "r"(b0), "r"(b1));
}
__device__ __forceinline__ void mma_z(float* d, const uint32_t* a, uint32_t b0, uint32_t b1) {
    asm volatile(
        "mma.sync.aligned.m16n8k8.row.col.f32.tf32.tf32.f32 "
        "{%0,%1,%2,%3}, {%4,%5,%6,%7}, {%8,%9}, {%10,%11,%12,%13};"
        : "=f"(d[0]), "=f"(d[1]), "=f"(d[2]), "=f"(d[3])
        : "r"(a[0]), "r"(a[1]), "r"(a[2]), "r"(a[3]), "r"(b0), "r"(b1),
          "f"(0.f), "f"(0.f), "f"(0.f), "f"(0.f));
}
__device__ __forceinline__ void mma8(float* d, const uint32_t* a, const uint32_t* b) {
    asm volatile(
        "mma.sync.aligned.m16n8k8.row.col.f32.tf32.tf32.f32 "
        "{%0,%1,%2,%3}, {%4,%5,%6,%7}, {%8,%9}, {%0,%1,%2,%3};"
        : "+f"(d[0]), "+f"(d[1]), "+f"(d[2]), "+f"(d[3])
        : "r"(a[0]), "r"(a[1]), "r"(a[2]), "r"(a[3]), "r"(b[0]), "r"(b[1]));
}

// ---------------- kernel 1: BN + ReLU + transpose -> xrT[b][p][c] (tf32) -----
__global__ void __launch_bounds__(256) bnT_kernel(
    const float* __restrict__ x, const float* __restrict__ gamma,
    const float* __restrict__ beta, const float* __restrict__ rmean,
    const float* __restrict__ rvar)
{
    __shared__ float s[32][33];
    const int pb = blockIdx.x, cb = blockIdx.y, b = blockIdx.z;
    const int tx = threadIdx.x, ty = threadIdx.y;     // 32 x 8
#pragma unroll
    for (int k = 0; k < 4; k++) {
        int cl = ty + k * 8;
        int c = cb * 32 + cl;
        float a = gamma[c] * rsqrtf(rvar[c] + 1e-5f);
        float bia = beta[c] - rmean[c] * a;
        float v = fmaxf(fmaf(x[(b * 256 + c) * 1024 + pb * 32 + tx], a, bia), 0.f);
        s[cl][tx] = v;
    }
    __syncthreads();
#pragma unroll
    for (int k = 0; k < 4; k++) {
        int pl = ty + k * 8;
        int p = pb * 32 + pl;
        g_xrT[(b * 1024 + p) * 256 + cb * 32 + tx] = tf32r(s[tx][pl]);
    }
}

// ---------------- kernel 2: pack A rows: conv taps (flipped) + wk + wv -------
__global__ void __launch_bounds__(256) wpack_kernel(
    const float* __restrict__ w_sc, const float* __restrict__ w_q,
    const float* __restrict__ w_k, const float* __restrict__ w_v)
{
    int i = blockIdx.x * 256 + threadIdx.x;           // [0, 1920*256)
    int m = i >> 8, c = i & 255;
    float v = 0.f;
    if (m < 1728) {
        int t = m / NCO, co = m - t * NCO;
        int s = 8 - t;                                 // spatial flip (verified)
        if (co < 128) v = w_sc[(c * 128 + co) * 9 + s];
        else          v = w_q[(c * 64 + (co - 128)) * 9 + s];
    } else if (m < 1792) {
        v = w_k[(m - 1728) * 256 + c];
    } else if (m < 1856) {
        v = w_v[(m - 1792) * 256 + c];
    }
    g_wA[i] = tf32r(v);
}

// ---------------- kernel 3: warp-MMA tf32 GEMM  Y = [Wconv;Wk;Wv] x X^T ------
#define SSTR 36
__global__ void __launch_bounds__(256) gemm_kernel() {
    __shared__ __align__(16) float As[128 * SSTR];
    __shared__ __align__(16) float Bs[128 * SSTR];
    const int tid = threadIdx.x;
    const int wid = tid >> 5, lane = tid & 31;
    const int nt = blockIdx.x, mt = blockIdx.y;
    const int wm = wid & 1, wn = wid >> 1;            // 2 x 4
    const int g = lane >> 2, tg = lane & 3;

    float acc[4][4][4];
#pragma unroll
    for (int mi = 0; mi < 4; mi++)
#pragma unroll
        for (int ni = 0; ni < 4; ni++)
#pragma unroll
            for (int q = 0; q < 4; q++) acc[mi][ni][q] = 0.f;

    for (int kc = 0; kc < 8; kc++) {
#pragma unroll
        for (int i = 0; i < 4; i++) {
            int fl = i * 256 + tid;                    // float4 idx, 8 per row
            int row = fl >> 3, k4 = fl & 7;
            float4 va = *(const float4*)(g_wA + (size_t)(mt * 128 + row) * 256 + kc * 32 + k4 * 4);
            *(float4*)&As[row * SSTR + k4 * 4] = va;
            float4 vb = *(const float4*)(g_xrT + (size_t)(nt * 128 + row) * 256 + kc * 32 + k4 * 4);
            *(float4*)&Bs[row * SSTR + k4 * 4] = vb;
        }
        __syncthreads();

#pragma unroll
        for (int ks = 0; ks < 4; ks++) {
            uint32_t a[4][4], b[4][2];
#pragma unroll
            for (int mi = 0; mi < 4; mi++) {
                const float* ap = &As[(wm * 64 + mi * 16) * SSTR + ks * 8];
                a[mi][0] = __float_as_uint(ap[g * SSTR + tg]);
                a[mi][1] = __float_as_uint(ap[(g + 8) * SSTR + tg]);
                a[mi][2] = __float_as_uint(ap[g * SSTR + tg + 4]);
                a[mi][3] = __float_as_uint(ap[(g + 8) * SSTR + tg + 4]);
            }
#pragma unroll
            for (int ni = 0; ni < 4; ni++) {
                const float* bp = &Bs[(wn * 32 + ni * 8) * SSTR + ks * 8];
                b[ni][0] = __float_as_uint(bp[g * SSTR + tg]);
                b[ni][1] = __float_as_uint(bp[g * SSTR + tg + 4]);
            }
#pragma unroll
            for (int mi = 0; mi < 4; mi++)
#pragma unroll
                for (int ni = 0; ni < 4; ni++)
                    mma8(acc[mi][ni], a[mi], b[ni]);
        }
        __syncthreads();
    }

#pragma unroll
    for (int mi = 0; mi < 4; mi++) {
#pragma unroll
        for (int ni = 0; ni < 4; ni++) {
            int row0 = mt * 128 + wm * 64 + mi * 16 + g;
            int col  = nt * 128 + wn * 32 + ni * 8 + 2 * tg;
            float2 v0 = make_float2(acc[mi][ni][0], acc[mi][ni][1]);
            float2 v1 = make_float2(acc[mi][ni][2], acc[mi][ni][3]);
            *(float2*)(g_Y + (size_t)row0 * NTOT + col) = v0;
            *(float2*)(g_Y + (size_t)(row0 + 8) * NTOT + col) = v1;
        }
    }
}

// ---------------- kernel 4: tap-gather  Y -> out(shortcut) + g_q -------------
__global__ void __launch_bounds__(256) gather_kernel(float* __restrict__ out) {
    const int y = blockIdx.x, b = blockIdx.y, half = blockIdx.z;

    int tys[2], iys[2], nyy = 0;
    if (y & 1) { tys[0] = 1; iys[0] = y >> 1; nyy = 1; }
    else {
        if ((y >> 1) <= 31)    { tys[nyy] = 0; iys[nyy] = y >> 1;       nyy++; }
        if ((y >> 1) - 1 >= 0) { tys[nyy] = 2; iys[nyy] = (y >> 1) - 1; nyy++; }
    }

    const int lim = (half + 1) * 6240;                // 96 co * 65 x per half
    for (int idx = half * 6240 + threadIdx.x; idx < lim; idx += 256) {
        int co = idx / 65;
        int x = idx - co * 65;
        int txs[2], ixs[2], nxx = 0;
        if (x & 1) { txs[0] = 1; ixs[0] = x >> 1; nxx = 1; }
        else {
            if ((x >> 1) <= 31)    { txs[nxx] = 0; ixs[nxx] = x >> 1;       nxx++; }
            if ((x >> 1) - 1 >= 0) { txs[nxx] = 2; ixs[nxx] = (x >> 1) - 1; nxx++; }
        }
        float s = 0.f;
        for (int yi = 0; yi < nyy; yi++)
            for (int xi = 0; xi < nxx; xi++) {
                int t = tys[yi] * 3 + txs[xi];
                s += g_Y[(size_t)(t * NCO + co) * NTOT + b * 1024 + iys[yi] * 32 + ixs[xi]];
            }
        int n = y * 65 + x;
        if (co < 128) out[(b * 128 + co) * NQ + n] = s;
        else          g_q[(b * 64 + (co - 128)) * NQ + n] = s;
    }
}

// ---------------- kernel 5: tensor-core attention ----------------------------
// CTA = 128 q rows x one (b,h); warp = 16 q rows. 16 chunks of 64 keys.
// QK: A=Q frags (registers, whole kernel), B=K from smem.  P=2^S via ex2,
// staged in per-warp smem slab (stride 68 => conflict-free A-frag reads).
// PV: A=P, B=V.  L (row sums): A=P (same frags!), B=ones => tf32 truncation of
// P cancels exactly between O and L.
__global__ void __launch_bounds__(256) attn2_kernel() {
    __shared__ float sKc[64 * 9];
    __shared__ float sVc[64 * 9];
    __shared__ float sP[8][16 * 68];
    const int qt = blockIdx.x, h = blockIdx.y, b = blockIdx.z;
    const int tid = threadIdx.x, wid = tid >> 5, lane = tid & 31;
    const int g = lane >> 2, tg = lane & 3;
    const int n0 = qt * 128 + wid * 16;
    const float sc = 0.35355339059327373f * 1.4426950408889634f;  // 1/sqrt(dk)*log2(e)

    uint32_t qf[4];
    {
        const float* qb = g_q + (size_t)(b * 64 + h * 8) * NQ;
        int nA = n0 + g, nB = n0 + 8 + g;
        float v0 = (nA < NQ) ? tf32r(qb[(size_t)tg * NQ + nA] * sc) : 0.f;
        float v1 = (nB < NQ) ? tf32r(qb[(size_t)tg * NQ + nB] * sc) : 0.f;
        float v2 = (nA < NQ) ? tf32r(qb[(size_t)(tg + 4) * NQ + nA] * sc) : 0.f;
        float v3 = (nB < NQ) ? tf32r(qb[(size_t)(tg + 4) * NQ + nB] * sc) : 0.f;
        qf[0] = __float_as_uint(v0); qf[1] = __float_as_uint(v1);
        qf[2] = __float_as_uint(v2); qf[3] = __float_as_uint(v3);
    }

    float oacc[4] = {0.f, 0.f, 0.f, 0.f};
    float lacc[4] = {0.f, 0.f, 0.f, 0.f};
    const uint32_t one = 0x3f800000u;
    float* Pw = sP[wid];

    const int dld = tid >> 5;                          // 0..7
    const int kld = (tid & 31) * 2;
    const float* srcK = g_Y + (size_t)(1728 + h * 8 + dld) * NTOT + b * 1024 + kld;
    const float* srcV = g_Y + (size_t)(1792 + h * 8 + dld) * NTOT + b * 1024 + kld;

    for (int ch = 0; ch < 16; ch++) {
        __syncthreads();
        {
            float2 k2 = *(const float2*)(srcK + ch * 64);
            sKc[(kld + 0) * 9 + dld] = tf32r(k2.x);
            sKc[(kld + 1) * 9 + dld] = tf32r(k2.y);
            float2 v2 = *(const float2*)(srcV + ch * 64);
            sVc[(kld + 0) * 9 + dld] = tf32r(v2.x);
            sVc[(kld + 1) * 9 + dld] = tf32r(v2.y);
        }
        __syncthreads();

        // phase 1: S = Q K^T (16q x 64k), P = 2^S -> slab
#pragma unroll
        for (int kk = 0; kk < 8; kk++) {
            uint32_t kf0 = __float_as_uint(sKc[(kk * 8 + g) * 9 + tg]);     // (k=n col g, d=tg)
            uint32_t kf1 = __float_as_uint(sKc[(kk * 8 + g) * 9 + tg + 4]);
            float s[4];
            mma_z(s, qf, kf0, kf1);
            float2 p01 = make_float2(ex2f(s[0]), ex2f(s[1]));
            float2 p23 = make_float2(ex2f(s[2]), ex2f(s[3]));
            *(float2*)&Pw[g * 68 + kk * 8 + 2 * tg] = p01;
            *(float2*)&Pw[(g + 8) * 68 + kk * 8 + 2 * tg] = p23;
        }
        __syncwarp();

        // phase 2: O += P V, L += P * ones  (same P frags)
#pragma unroll
        for (int ks = 0; ks < 8; ks++) {
            uint32_t af[4];
            af[0] = __float_as_uint(Pw[g * 68 + ks * 8 + tg]);
            af[1] = __float_as_uint(Pw[(g + 8) * 68 + ks * 8 + tg]);
            af[2] = __float_as_uint(Pw[g * 68 + ks * 8 + tg + 4]);
            af[3] = __float_as_uint(Pw[(g + 8) * 68 + ks * 8 + tg + 4]);
            uint32_t vb0 = __float_as_uint(sVc[(ks * 8 + tg) * 9 + g]);     // (k=tg, d=g)
            uint32_t vb1 = __float_as_uint(sVc[(ks * 8 + tg + 4) * 9 + g]);
            mma_acc(oacc, af, vb0, vb1);
            mma_acc(lacc, af, one, one);
        }
    }

    // epilogue: normalize, store (C layout: rows g/g+8, cols 2tg/2tg+1 = d)
    float* ob = g_attO + (size_t)(b * 64 + h * 8) * NQ;
    int nA = n0 + g, nB = n0 + 8 + g;
    if (nA < NQ) {
        float inv = 1.f / lacc[0];
        ob[(size_t)(2 * tg) * NQ + nA]     = oacc[0] * inv;
        ob[(size_t)(2 * tg + 1) * NQ + nA] = oacc[1] * inv;
    }
    if (nB < NQ) {
        float inv = 1.f / lacc[2];
        ob[(size_t)(2 * tg) * NQ + nB]     = oacc[2] * inv;
        ob[(size_t)(2 * tg + 1) * NQ + nB] = oacc[3] * inv;
    }
}

// ---------------- kernel 6: output projection + residual add -----------------
__global__ void __launch_bounds__(256) proj_kernel(
    const float* __restrict__ w_o, float* __restrict__ out)
{
    __shared__ float sw[32 * 64];
    const int cog = blockIdx.z, b = blockIdx.y;
    for (int i = threadIdx.x; i < 2048; i += 256) sw[i] = w_o[cog * 2048 + i];
    __syncthreads();

    const int nl = threadIdx.x & 63;
    const int sub = threadIdx.x >> 6;                  // 0..3 (8 co each)
    const int n = blockIdx.x * 64 + nl;
    if (n >= NQ) return;

    ull a2[32];
#pragma unroll
    for (int dd = 0; dd < 32; dd++) {
        float a0 = g_attO[(size_t)(b * 64 + 2 * dd) * NQ + n];
        float a1 = g_attO[(size_t)(b * 64 + 2 * dd + 1) * NQ + n];
        a2[dd] = pk2(a0, a1);
    }

#pragma unroll
    for (int c0 = 0; c0 < 8; c0++) {
        int cl = sub * 8 + c0;
        const ull* wr = (const ull*)(sw + cl * 64);
        ull s2 = 0ull;
#pragma unroll
        for (int dd = 0; dd < 32; dd++)
            s2 = ffma2(a2[dd], wr[dd], s2);
        float s0, s1; upk2(s2, s0, s1);
        int co = cog * 32 + cl;
        out[(size_t)(b * 128 + co) * NQ + n] += s0 + s1;
    }
}

// ---------------- launcher ---------------------------------------------------
extern "C" void kernel_launch(void* const* d_in, const int* in_sizes, int n_in,
                              void* d_out, int out_size)
{
    const float* x     = (const float*)d_in[0];
    const float* gamma = (const float*)d_in[1];
    const float* beta  = (const float*)d_in[2];
    const float* rmean = (const float*)d_in[3];
    const float* rvar  = (const float*)d_in[4];
    const float* w_sc  = (const float*)d_in[5];
    const float* w_q   = (const float*)d_in[6];
    const float* w_k   = (const float*)d_in[7];
    const float* w_v   = (const float*)d_in[8];
    const float* w_o   = (const float*)d_in[9];
    float* out = (float*)d_out;

    bnT_kernel<<<dim3(32, 8, 4), dim3(32, 8)>>>(x, gamma, beta, rmean, rvar);
    wpack_kernel<<<1920, 256>>>(w_sc, w_q, w_k, w_v);
    gemm_kernel<<<dim3(32, 15), 256>>>();
    gather_kernel<<<dim3(65, 4, 2), 256>>>(out);
    attn2_kernel<<<dim3(34, 8, 4), 256>>>();
    proj_kernel<<<dim3(67, 4, 4), 256>>>(w_o, out);
}

// round 9
// speedup vs baseline: 3.2682x; 1.1216x over previous
#include <cuda_runtime.h>
#include <cstdint>

#define BB 4
#define CC 256
#define NQ 4225        // 65*65
#define NCO 192        // 128 shortcut + 64 q
#define MPAD 1920      // 1728 conv + 64 k + 64 v, padded to 15*128
#define NTOT 4096      // 4 b * 1024 p

typedef unsigned long long ull;

// ---------------- scratch (device globals; no allocation allowed) ------------
__device__ float g_xrT[BB * 1024 * CC];       // BN+ReLU, transposed [b][p][c] (tf32-rounded)
__device__ float g_wA[MPAD * CC];             // GEMM A rows: conv taps (flipped) + wk + wv
__device__ float g_Y[MPAD * NTOT];            // GEMM result [m][n=b*1024+p]
__device__ float g_q[BB * 64 * NQ];           // q conv output  [b][d][n]
__device__ float g_attO[BB * 64 * NQ];        // attention out  [b][d][n]

// ---------------- helpers ----------------------------------------------------
__device__ __forceinline__ ull pk2(float a, float b) {
    ull r; asm("mov.b64 %0, {%1,%2};" : "=l"(r) : "f"(a), "f"(b)); return r;
}
__device__ __forceinline__ void upk2(ull v, float& a, float& b) {
    asm("mov.b64 {%0,%1}, %2;" : "=f"(a), "=f"(b) : "l"(v));
}
__device__ __forceinline__ ull ffma2(ull a, ull b, ull c) {
    ull r; asm("fma.rn.f32x2 %0, %1, %2, %3;" : "=l"(r) : "l"(a), "l"(b), "l"(c)); return r;
}
__device__ __forceinline__ float ex2f(float x) {
    float r; asm("ex2.approx.f32 %0, %1;" : "=f"(r) : "f"(x)); return r;
}
__device__ __forceinline__ float tf32r(float x) {   // round-to-nearest tf32
    float r; asm("cvt.rna.tf32.f32 %0, %1;" : "=f"(r) : "f"(x)); return r;
}

// mma.sync m16n8k8 tf32. Frag layouts (PTX, verified R7/R8):
//  A: a0=(g,tg) a1=(g+8,tg) a2=(g,tg+4) a3=(g+8,tg+4)
//  B: b0=(k=tg, n=g) b1=(k=tg+4, n=g)
//  C: c0=(g,2tg) c1=(g,2tg+1) c2=(g+8,2tg) c3=(g+8,2tg+1)
__device__ __forceinline__ void mma_acc(float* d, const uint32_t* a, uint32_t b0, uint32_t b1) {
    asm volatile(
        "mma.sync.aligned.m16n8k8.row.col.f32.tf32.tf32.f32 "
        "{%0,%1,%2,%3}, {%4,%5,%6,%7}, {%8,%9}, {%0,%1,%2,%3};"
        : "+f"(d[0]), "+f"(d[1]), "+f"(d[2]), "+f"(d[3])
        : "r"(a[0]), "r"(a[1]), "r"(a[2]), "r"(a[3]), "r"(b0), "r"(b1));
}
__device__ __forceinline__ void mma_z(float* d, const uint32_t* a, uint32_t b0, uint32_t b1) {
    asm volatile(
        "mma.sync.aligned.m16n8k8.row.col.f32.tf32.tf32.f32 "
        "{%0,%1,%2,%3}, {%4,%5,%6,%7}, {%8,%9}, {%10,%11,%12,%13};"
        : "=f"(d[0]), "=f"(d[1]), "=f"(d[2]), "=f"(d[3])
        : "r"(a[0]), "r"(a[1]), "r"(a[2]), "r"(a[3]), "r"(b0), "r"(b1),
          "f"(0.f), "f"(0.f), "f"(0.f), "f"(0.f));
}
__device__ __forceinline__ void mma8(float* d, const uint32_t* a, const uint32_t* b) {
    asm volatile(
        "mma.sync.aligned.m16n8k8.row.col.f32.tf32.tf32.f32 "
        "{%0,%1,%2,%3}, {%4,%5,%6,%7}, {%8,%9}, {%0,%1,%2,%3};"
        : "+f"(d[0]), "+f"(d[1]), "+f"(d[2]), "+f"(d[3])
        : "r"(a[0]), "r"(a[1]), "r"(a[2]), "r"(a[3]), "r"(b[0]), "r"(b[1]));
}

// ---------------- kernel 1: BN + ReLU + transpose -> xrT[b][p][c] (tf32) -----
__global__ void __launch_bounds__(256) bnT_kernel(
    const float* __restrict__ x, const float* __restrict__ gamma,
    const float* __restrict__ beta, const float* __restrict__ rmean,
    const float* __restrict__ rvar)
{
    __shared__ float s[32][33];
    const int pb = blockIdx.x, cb = blockIdx.y, b = blockIdx.z;
    const int tx = threadIdx.x, ty = threadIdx.y;     // 32 x 8
#pragma unroll
    for (int k = 0; k < 4; k++) {
        int cl = ty + k * 8;
        int c = cb * 32 + cl;
        float a = gamma[c] * rsqrtf(rvar[c] + 1e-5f);
        float bia = beta[c] - rmean[c] * a;
        float v = fmaxf(fmaf(x[(b * 256 + c) * 1024 + pb * 32 + tx], a, bia), 0.f);
        s[cl][tx] = v;
    }
    __syncthreads();
#pragma unroll
    for (int k = 0; k < 4; k++) {
        int pl = ty + k * 8;
        int p = pb * 32 + pl;
        g_xrT[(b * 1024 + p) * 256 + cb * 32 + tx] = tf32r(s[tx][pl]);
    }
}

// ---------------- kernel 2: pack A rows: conv taps (flipped) + wk + wv -------
__global__ void __launch_bounds__(256) wpack_kernel(
    const float* __restrict__ w_sc, const float* __restrict__ w_q,
    const float* __restrict__ w_k, const float* __restrict__ w_v)
{
    int i = blockIdx.x * 256 + threadIdx.x;           // [0, 1920*256)
    int m = i >> 8, c = i & 255;
    float v = 0.f;
    if (m < 1728) {
        int t = m / NCO, co = m - t * NCO;
        int s = 8 - t;                                 // spatial flip (verified)
        if (co < 128) v = w_sc[(c * 128 + co) * 9 + s];
        else          v = w_q[(c * 64 + (co - 128)) * 9 + s];
    } else if (m < 1792) {
        v = w_k[(m - 1728) * 256 + c];
    } else if (m < 1856) {
        v = w_v[(m - 1792) * 256 + c];
    }
    g_wA[i] = tf32r(v);
}

// ---------------- kernel 3: warp-MMA tf32 GEMM  Y = [Wconv;Wk;Wv] x X^T ------
#define SSTR 36
__global__ void __launch_bounds__(256) gemm_kernel() {
    __shared__ __align__(16) float As[128 * SSTR];
    __shared__ __align__(16) float Bs[128 * SSTR];
    const int tid = threadIdx.x;
    const int wid = tid >> 5, lane = tid & 31;
    const int nt = blockIdx.x, mt = blockIdx.y;
    const int wm = wid & 1, wn = wid >> 1;            // 2 x 4
    const int g = lane >> 2, tg = lane & 3;

    float acc[4][4][4];
#pragma unroll
    for (int mi = 0; mi < 4; mi++)
#pragma unroll
        for (int ni = 0; ni < 4; ni++)
#pragma unroll
            for (int q = 0; q < 4; q++) acc[mi][ni][q] = 0.f;

    for (int kc = 0; kc < 8; kc++) {
#pragma unroll
        for (int i = 0; i < 4; i++) {
            int fl = i * 256 + tid;                    // float4 idx, 8 per row
            int row = fl >> 3, k4 = fl & 7;
            float4 va = *(const float4*)(g_wA + (size_t)(mt * 128 + row) * 256 + kc * 32 + k4 * 4);
            *(float4*)&As[row * SSTR + k4 * 4] = va;
            float4 vb = *(const float4*)(g_xrT + (size_t)(nt * 128 + row) * 256 + kc * 32 + k4 * 4);
            *(float4*)&Bs[row * SSTR + k4 * 4] = vb;
        }
        __syncthreads();

#pragma unroll
        for (int ks = 0; ks < 4; ks++) {
            uint32_t a[4][4], b[4][2];
#pragma unroll
            for (int mi = 0; mi < 4; mi++) {
                const float* ap = &As[(wm * 64 + mi * 16) * SSTR + ks * 8];
                a[mi][0] = __float_as_uint(ap[g * SSTR + tg]);
                a[mi][1] = __float_as_uint(ap[(g + 8) * SSTR + tg]);
                a[mi][2] = __float_as_uint(ap[g * SSTR + tg + 4]);
                a[mi][3] = __float_as_uint(ap[(g + 8) * SSTR + tg + 4]);
            }
#pragma unroll
            for (int ni = 0; ni < 4; ni++) {
                const float* bp = &Bs[(wn * 32 + ni * 8) * SSTR + ks * 8];
                b[ni][0] = __float_as_uint(bp[g * SSTR + tg]);
                b[ni][1] = __float_as_uint(bp[g * SSTR + tg + 4]);
            }
#pragma unroll
            for (int mi = 0; mi < 4; mi++)
#pragma unroll
                for (int ni = 0; ni < 4; ni++)
                    mma8(acc[mi][ni], a[mi], b[ni]);
        }
        __syncthreads();
    }

#pragma unroll
    for (int mi = 0; mi < 4; mi++) {
#pragma unroll
        for (int ni = 0; ni < 4; ni++) {
            int row0 = mt * 128 + wm * 64 + mi * 16 + g;
            int col  = nt * 128 + wn * 32 + ni * 8 + 2 * tg;
            float2 v0 = make_float2(acc[mi][ni][0], acc[mi][ni][1]);
            float2 v1 = make_float2(acc[mi][ni][2], acc[mi][ni][3]);
            *(float2*)(g_Y + (size_t)row0 * NTOT + col) = v0;
            *(float2*)(g_Y + (size_t)(row0 + 8) * NTOT + col) = v1;
        }
    }
}

// ---------------- kernel 4: tap-gather  Y -> out(shortcut) + g_q -------------
// z-split by 8 co-groups of 24 -> 2080 CTAs, ~6 independent iters/thread.
__global__ void __launch_bounds__(256) gather_kernel(float* __restrict__ out) {
    const int y = blockIdx.x, b = blockIdx.y, zg = blockIdx.z;

    int tys[2], iys[2], nyy = 0;
    if (y & 1) { tys[0] = 1; iys[0] = y >> 1; nyy = 1; }
    else {
        if ((y >> 1) <= 31)    { tys[nyy] = 0; iys[nyy] = y >> 1;       nyy++; }
        if ((y >> 1) - 1 >= 0) { tys[nyy] = 2; iys[nyy] = (y >> 1) - 1; nyy++; }
    }

    const int base = zg * 1560;                        // 24 co * 65 x per group
    const int lim  = base + 1560;
    for (int idx = base + threadIdx.x; idx < lim; idx += 256) {
        int co = idx / 65;
        int x = idx - co * 65;
        int txs[2], ixs[2], nxx = 0;
        if (x & 1) { txs[0] = 1; ixs[0] = x >> 1; nxx = 1; }
        else {
            if ((x >> 1) <= 31)    { txs[nxx] = 0; ixs[nxx] = x >> 1;       nxx++; }
            if ((x >> 1) - 1 >= 0) { txs[nxx] = 2; ixs[nxx] = (x >> 1) - 1; nxx++; }
        }
        float s = 0.f;
        for (int yi = 0; yi < nyy; yi++)
            for (int xi = 0; xi < nxx; xi++) {
                int t = tys[yi] * 3 + txs[xi];
                s += __ldg(g_Y + (size_t)(t * NCO + co) * NTOT + b * 1024 + iys[yi] * 32 + ixs[xi]);
            }
        int n = y * 65 + x;
        if (co < 128) out[(b * 128 + co) * NQ + n] = s;
        else          g_q[(b * 64 + (co - 128)) * NQ + n] = s;
    }
}

// ---------------- kernel 5: tensor-core attention, shuffle-relayout P --------
// CTA = 128 q rows x one (b,h); warp = 16 q rows. 16 chunks of 64 keys.
// Each QK mma yields one 16x8 S block; P=2^S is relayouted C-frag -> A-frag
// via 8 SHFL + 4 selects (no smem slab -> 4.6KB smem, high occupancy).
// L-mma consumes the SAME A-frags as PV -> tf32 truncation cancels in O/L.
__global__ void __launch_bounds__(256) attn2_kernel() {
    __shared__ float sKc[64 * 9];
    __shared__ float sVc[64 * 9];
    const int qt = blockIdx.x, h = blockIdx.y, b = blockIdx.z;
    const int tid = threadIdx.x, wid = tid >> 5, lane = tid & 31;
    const int g = lane >> 2, tg = lane & 3;
    const int n0 = qt * 128 + wid * 16;
    const float sc = 0.35355339059327373f * 1.4426950408889634f;  // 1/sqrt(dk)*log2(e)

    uint32_t qf[4];
    {
        const float* qb = g_q + (size_t)(b * 64 + h * 8) * NQ;
        int nA = n0 + g, nB = n0 + 8 + g;
        float v0 = (nA < NQ) ? tf32r(qb[(size_t)tg * NQ + nA] * sc) : 0.f;
        float v1 = (nB < NQ) ? tf32r(qb[(size_t)tg * NQ + nB] * sc) : 0.f;
        float v2 = (nA < NQ) ? tf32r(qb[(size_t)(tg + 4) * NQ + nA] * sc) : 0.f;
        float v3 = (nB < NQ) ? tf32r(qb[(size_t)(tg + 4) * NQ + nB] * sc) : 0.f;
        qf[0] = __float_as_uint(v0); qf[1] = __float_as_uint(v1);
        qf[2] = __float_as_uint(v2); qf[3] = __float_as_uint(v3);
    }

    float oacc[4] = {0.f, 0.f, 0.f, 0.f};
    float lacc[4] = {0.f, 0.f, 0.f, 0.f};
    const uint32_t one = 0x3f800000u;
    const int src0 = g * 4 + (tg >> 1);
    const int src2 = src0 + 2;
    const bool e = tg & 1;

    const int dld = tid >> 5;                          // 0..7
    const int kld = (tid & 31) * 2;
    const float* srcK = g_Y + (size_t)(1728 + h * 8 + dld) * NTOT + b * 1024 + kld;
    const float* srcV = g_Y + (size_t)(1792 + h * 8 + dld) * NTOT + b * 1024 + kld;

    for (int ch = 0; ch < 16; ch++) {
        __syncthreads();
        {
            float2 k2 = *(const float2*)(srcK + ch * 64);
            sKc[(kld + 0) * 9 + dld] = tf32r(k2.x);
            sKc[(kld + 1) * 9 + dld] = tf32r(k2.y);
            float2 v2 = *(const float2*)(srcV + ch * 64);
            sVc[(kld + 0) * 9 + dld] = tf32r(v2.x);
            sVc[(kld + 1) * 9 + dld] = tf32r(v2.y);
        }
        __syncthreads();

#pragma unroll
        for (int kk = 0; kk < 8; kk++) {
            // S block = Q x K^T  (16q x 8k)
            uint32_t kf0 = __float_as_uint(sKc[(kk * 8 + g) * 9 + tg]);
            uint32_t kf1 = __float_as_uint(sKc[(kk * 8 + g) * 9 + tg + 4]);
            float s[4];
            mma_z(s, qf, kf0, kf1);
            float p0 = ex2f(s[0]), p1 = ex2f(s[1]);
            float p2 = ex2f(s[2]), p3 = ex2f(s[3]);
            // C-frag -> A-frag lane permutation
            float q00 = __shfl_sync(0xffffffffu, p0, src0);
            float q01 = __shfl_sync(0xffffffffu, p1, src0);
            float q02 = __shfl_sync(0xffffffffu, p2, src0);
            float q03 = __shfl_sync(0xffffffffu, p3, src0);
            float q20 = __shfl_sync(0xffffffffu, p0, src2);
            float q21 = __shfl_sync(0xffffffffu, p1, src2);
            float q22 = __shfl_sync(0xffffffffu, p2, src2);
            float q23 = __shfl_sync(0xffffffffu, p3, src2);
            uint32_t af[4];
            af[0] = __float_as_uint(e ? q01 : q00);
            af[1] = __float_as_uint(e ? q03 : q02);
            af[2] = __float_as_uint(e ? q21 : q20);
            af[3] = __float_as_uint(e ? q23 : q22);
            // O += P V ; L += P * ones (same frags)
            uint32_t vb0 = __float_as_uint(sVc[(kk * 8 + tg) * 9 + g]);
            uint32_t vb1 = __float_as_uint(sVc[(kk * 8 + tg + 4) * 9 + g]);
            mma_acc(oacc, af, vb0, vb1);
            mma_acc(lacc, af, one, one);
        }
    }

    // epilogue: normalize, store (C layout: rows g/g+8, cols 2tg/2tg+1 = d)
    float* ob = g_attO + (size_t)(b * 64 + h * 8) * NQ;
    int nA = n0 + g, nB = n0 + 8 + g;
    if (nA < NQ) {
        float inv = 1.f / lacc[0];
        ob[(size_t)(2 * tg) * NQ + nA]     = oacc[0] * inv;
        ob[(size_t)(2 * tg + 1) * NQ + nA] = oacc[1] * inv;
    }
    if (nB < NQ) {
        float inv = 1.f / lacc[2];
        ob[(size_t)(2 * tg) * NQ + nB]     = oacc[2] * inv;
        ob[(size_t)(2 * tg + 1) * NQ + nB] = oacc[3] * inv;
    }
}

// ---------------- kernel 6: output projection + residual add -----------------
__global__ void __launch_bounds__(256) proj_kernel(
    const float* __restrict__ w_o, float* __restrict__ out)
{
    __shared__ float sw[32 * 64];
    const int cog = blockIdx.z, b = blockIdx.y;
    for (int i = threadIdx.x; i < 2048; i += 256) sw[i] = w_o[cog * 2048 + i];
    __syncthreads();

    const int nl = threadIdx.x & 63;
    const int sub = threadIdx.x >> 6;                  // 0..3 (8 co each)
    const int n = blockIdx.x * 64 + nl;
    if (n >= NQ) return;

    ull a2[32];
#pragma unroll
    for (int dd = 0; dd < 32; dd++) {
        float a0 = g_attO[(size_t)(b * 64 + 2 * dd) * NQ + n];
        float a1 = g_attO[(size_t)(b * 64 + 2 * dd + 1) * NQ + n];
        a2[dd] = pk2(a0, a1);
    }

#pragma unroll
    for (int c0 = 0; c0 < 8; c0++) {
        int cl = sub * 8 + c0;
        const ull* wr = (const ull*)(sw + cl * 64);
        ull s2 = 0ull;
#pragma unroll
        for (int dd = 0; dd < 32; dd++)
            s2 = ffma2(a2[dd], wr[dd], s2);
        float s0, s1; upk2(s2, s0, s1);
        int co = cog * 32 + cl;
        out[(size_t)(b * 128 + co) * NQ + n] += s0 + s1;
    }
}

// ---------------- launcher ---------------------------------------------------
extern "C" void kernel_launch(void* const* d_in, const int* in_sizes, int n_in,
                              void* d_out, int out_size)
{
    const float* x     = (const float*)d_in[0];
    const float* gamma = (const float*)d_in[1];
    const float* beta  = (const float*)d_in[2];
    const float* rmean = (const float*)d_in[3];
    const float* rvar  = (const float*)d_in[4];
    const float* w_sc  = (const float*)d_in[5];
    const float* w_q   = (const float*)d_in[6];
    const float* w_k   = (const float*)d_in[7];
    const float* w_v   = (const float*)d_in[8];
    const float* w_o   = (const float*)d_in[9];
    float* out = (float*)d_out;

    bnT_kernel<<<dim3(32, 8, 4), dim3(32, 8)>>>(x, gamma, beta, rmean, rvar);
    wpack_kernel<<<1920, 256>>>(w_sc, w_q, w_k, w_v);
    gemm_kernel<<<dim3(32, 15), 256>>>();
    gather_kernel<<<dim3(65, 4, 8), 256>>>(out);
    attn2_kernel<<<dim3(34, 8, 4), 256>>>();
    proj_kernel<<<dim3(67, 4, 4), 256>>>(w_o, out);
}